// round 1
// baseline (speedup 1.0000x reference)
#include <cuda_runtime.h>
#include <cuda_bf16.h>
#include <cstdint>
#include <cstddef>

// Problem dims
#define BB 4
#define TT 1024
#define EE 512
#define HH 8
#define LL 4
#define VV 32000
#define HIDN 100
#define HD 64
#define BT (BB*TT)          // 4096
#define BHT (BB*HH*TT)      // 32768
#define ATT_PER_L ((size_t)BB*HH*TT*TT)   // 33,554,432
#define LOGITS_N ((size_t)BT*VV)          // 131,072,000

// ---------------- scratch (device globals; no allocations allowed) ----------
__device__ float d_x[BT*EE];
__device__ float d_h[BT*EE];
__device__ float d_q[BT*EE];
__device__ float d_k[BT*EE];
__device__ float d_v[BT*EE];
__device__ float d_y[BT*EE];
__device__ float d_u[BT*HIDN];
__device__ float d_S[(size_t)BB*HH*TT*TT];   // raw scores, 128 MB

// ---------------- embed: x = tok_emb[idx] + pos_emb -------------------------
__global__ void embed_kernel(const int* __restrict__ idx,
                             const float* __restrict__ tok,
                             const float* __restrict__ pos,
                             float* __restrict__ x) {
    int row = blockIdx.x;            // 0..BT-1
    int t = row & (TT - 1);
    int token = idx[row];
    const float4* tp = (const float4*)(tok + (size_t)token * EE);
    const float4* pp = (const float4*)(pos + (size_t)t * EE);
    float4* xp = (float4*)(x + (size_t)row * EE);
    int c = threadIdx.x;             // 128 threads, E/4 = 128
    float4 a = tp[c], b = pp[c];
    xp[c] = make_float4(a.x + b.x, a.y + b.y, a.z + b.z, a.w + b.w);
}

// ---------------- layernorm --------------------------------------------------
__global__ void ln_kernel(const float* __restrict__ x, float* __restrict__ out,
                          const float* __restrict__ g, const float* __restrict__ b) {
    int row = blockIdx.x;
    int tid = threadIdx.x;           // 128 threads
    const float4* xp = (const float4*)(x + (size_t)row * EE);
    float4 v = xp[tid];
    float s = v.x + v.y + v.z + v.w;
    __shared__ float red[4];
    // sum
    for (int o = 16; o; o >>= 1) s += __shfl_xor_sync(~0u, s, o);
    if ((tid & 31) == 0) red[tid >> 5] = s;
    __syncthreads();
    float mean = (red[0] + red[1] + red[2] + red[3]) / (float)EE;
    float dx = v.x - mean, dy = v.y - mean, dz = v.z - mean, dw = v.w - mean;
    float ss = dx*dx + dy*dy + dz*dz + dw*dw;
    __syncthreads();
    for (int o = 16; o; o >>= 1) ss += __shfl_xor_sync(~0u, ss, o);
    if ((tid & 31) == 0) red[tid >> 5] = ss;
    __syncthreads();
    float var = (red[0] + red[1] + red[2] + red[3]) / (float)EE;
    float inv = 1.0f / sqrtf(var + 1e-5f);
    const float4* gp = (const float4*)g;
    const float4* bp = (const float4*)b;
    float4 gg = gp[tid], bb = bp[tid];
    float4* op = (float4*)(out + (size_t)row * EE);
    op[tid] = make_float4(dx*inv*gg.x + bb.x, dy*inv*gg.y + bb.y,
                          dz*inv*gg.z + bb.z, dw*inv*gg.w + bb.w);
}

// ---------------- generic tiled SGEMM: C = A@W (+bias)(+res)(relu) ----------
// A: MxK row-major, W: KxN row-major, C/res: MxN row-major.
template <bool RELU, bool BIAS, bool RES>
__global__ void sgemm_kernel(const float* __restrict__ A, const float* __restrict__ W,
                             const float* __restrict__ bias, const float* __restrict__ res,
                             float* __restrict__ C, int M, int N, int K) {
    const int BM = 64, BN = 64, BK = 16;
    __shared__ float As[BK][BM + 1];
    __shared__ float Bs[BK][BN + 1];
    int tid = threadIdx.x;           // 256
    int tr = tid >> 4, tc = tid & 15;
    int row0 = blockIdx.y * BM, col0 = blockIdx.x * BN;
    float acc[4][4] = {};
    for (int k0 = 0; k0 < K; k0 += BK) {
        #pragma unroll
        for (int j = 0; j < (BM*BK)/256; j++) {
            int i = tid + j * 256;
            int m = i / BK, kk = i % BK;
            int gr = row0 + m, gk = k0 + kk;
            As[kk][m] = (gr < M && gk < K) ? A[(size_t)gr * K + gk] : 0.0f;
        }
        #pragma unroll
        for (int j = 0; j < (BK*BN)/256; j++) {
            int i = tid + j * 256;
            int kk = i / BN, n = i % BN;
            int gk = k0 + kk, gc = col0 + n;
            Bs[kk][n] = (gk < K && gc < N) ? W[(size_t)gk * N + gc] : 0.0f;
        }
        __syncthreads();
        #pragma unroll
        for (int kk = 0; kk < BK; kk++) {
            float a[4], bv[4];
            #pragma unroll
            for (int i = 0; i < 4; i++) a[i] = As[kk][tr*4 + i];
            #pragma unroll
            for (int j = 0; j < 4; j++) bv[j] = Bs[kk][tc*4 + j];
            #pragma unroll
            for (int i = 0; i < 4; i++)
                #pragma unroll
                for (int j = 0; j < 4; j++)
                    acc[i][j] = fmaf(a[i], bv[j], acc[i][j]);
        }
        __syncthreads();
    }
    #pragma unroll
    for (int i = 0; i < 4; i++) {
        int r = row0 + tr*4 + i;
        if (r >= M) continue;
        #pragma unroll
        for (int j = 0; j < 4; j++) {
            int c = col0 + tc*4 + j;
            if (c >= N) continue;
            float v = acc[i][j];
            if (BIAS) v += bias[c];
            if (RES)  v += res[(size_t)r * N + c];
            if (RELU) v = fmaxf(v, 0.0f);
            C[(size_t)r * N + c] = v;
        }
    }
}

// ---------------- QK^T: S[bh, t, s] = scale * q . k (causal block skip) ------
__global__ void qk_kernel(const float* __restrict__ q, const float* __restrict__ k,
                          float* __restrict__ S) {
    int sb = blockIdx.x, tb = blockIdx.y, bh = blockIdx.z;
    if (sb > tb) return;                       // fully above diagonal
    int b = bh >> 3, h = bh & 7;
    const float* qp = q + ((size_t)b*TT + tb*64) * EE + h*HD;
    const float* kp = k + ((size_t)b*TT + sb*64) * EE + h*HD;
    __shared__ float Qs[64][HD + 1];
    __shared__ float Ks[64][HD + 1];
    int tid = threadIdx.x;                     // 256
    #pragma unroll
    for (int j = 0; j < 16; j++) {
        int i = tid + j * 256;
        int r = i >> 6, d = i & 63;
        Qs[r][d] = qp[(size_t)r * EE + d];
        Ks[r][d] = kp[(size_t)r * EE + d];
    }
    __syncthreads();
    int tr = tid >> 4, tc = tid & 15;
    float acc[4][4] = {};
    #pragma unroll
    for (int d = 0; d < HD; d++) {
        float a[4], bv[4];
        #pragma unroll
        for (int i = 0; i < 4; i++) a[i] = Qs[tr*4 + i][d];
        #pragma unroll
        for (int j = 0; j < 4; j++) bv[j] = Ks[tc*4 + j][d];
        #pragma unroll
        for (int i = 0; i < 4; i++)
            #pragma unroll
            for (int j = 0; j < 4; j++)
                acc[i][j] = fmaf(a[i], bv[j], acc[i][j]);
    }
    float* sp = S + ((size_t)bh * TT + tb*64) * TT + sb*64;
    #pragma unroll
    for (int i = 0; i < 4; i++)
        #pragma unroll
        for (int j = 0; j < 4; j++)
            sp[(size_t)(tr*4 + i) * TT + tc*4 + j] = acc[i][j] * 0.125f;
}

// ---------------- causal softmax row -> writes attn map into d_out ----------
__global__ void softmax_kernel(const float* __restrict__ S, float* __restrict__ out) {
    int row = blockIdx.x;                      // bh*T + t
    int t = row & (TT - 1);
    const float* sp = S + (size_t)row * TT;
    float* op = out + (size_t)row * TT;
    int tid = threadIdx.x;                     // 256
    float vals[4];
    float m = -1e30f;
    #pragma unroll
    for (int i = 0; i < 4; i++) {
        int s = tid + i * 256;
        vals[i] = (s <= t) ? sp[s] : -1e30f;
        m = fmaxf(m, vals[i]);
    }
    __shared__ float red[8];
    for (int o = 16; o; o >>= 1) m = fmaxf(m, __shfl_xor_sync(~0u, m, o));
    if ((tid & 31) == 0) red[tid >> 5] = m;
    __syncthreads();
    m = red[0];
    #pragma unroll
    for (int i = 1; i < 8; i++) m = fmaxf(m, red[i]);
    float e[4];
    float ssum = 0.0f;
    #pragma unroll
    for (int i = 0; i < 4; i++) {
        int s = tid + i * 256;
        e[i] = (s <= t) ? expf(vals[i] - m) : 0.0f;
        ssum += e[i];
    }
    __syncthreads();
    for (int o = 16; o; o >>= 1) ssum += __shfl_xor_sync(~0u, ssum, o);
    if ((tid & 31) == 0) red[tid >> 5] = ssum;
    __syncthreads();
    float tot = 0.0f;
    #pragma unroll
    for (int i = 0; i < 8; i++) tot += red[i];
    float inv = 1.0f / tot;
    #pragma unroll
    for (int i = 0; i < 4; i++) {
        int s = tid + i * 256;
        op[s] = e[i] * inv;                    // 0 above diagonal
    }
}

// ---------------- Y = P @ V (P read back from d_out attn region) ------------
__global__ void av_kernel(const float* __restrict__ P, const float* __restrict__ v,
                          float* __restrict__ y) {
    int tb = blockIdx.x, bh = blockIdx.z;
    int b = bh >> 3, h = bh & 7;
    const float* pp = P + ((size_t)bh * TT + tb*64) * TT;
    __shared__ float Ps[64][33];
    __shared__ float Vs[32][65];
    int tid = threadIdx.x;                     // 256
    int tr = tid >> 4, tc = tid & 15;
    float acc[4][4] = {};
    int send = tb*64 + 64;                     // causal: P[t,s]=0 for s>t
    for (int s0 = 0; s0 < send; s0 += 32) {
        #pragma unroll
        for (int j = 0; j < 8; j++) {
            int i = tid + j * 256;
            int m = i >> 5, kk = i & 31;
            Ps[m][kk] = pp[(size_t)m * TT + s0 + kk];
        }
        #pragma unroll
        for (int j = 0; j < 8; j++) {
            int i = tid + j * 256;
            int kk = i >> 6, d = i & 63;
            Vs[kk][d] = v[((size_t)b*TT + s0 + kk) * EE + h*HD + d];
        }
        __syncthreads();
        #pragma unroll
        for (int kk = 0; kk < 32; kk++) {
            float a[4], bv[4];
            #pragma unroll
            for (int i = 0; i < 4; i++) a[i] = Ps[tr*4 + i][kk];
            #pragma unroll
            for (int j = 0; j < 4; j++) bv[j] = Vs[kk][tc*4 + j];
            #pragma unroll
            for (int i = 0; i < 4; i++)
                #pragma unroll
                for (int j = 0; j < 4; j++)
                    acc[i][j] = fmaf(a[i], bv[j], acc[i][j]);
        }
        __syncthreads();
    }
    #pragma unroll
    for (int i = 0; i < 4; i++)
        #pragma unroll
        for (int j = 0; j < 4; j++)
            y[((size_t)b*TT + tb*64 + tr*4 + i) * EE + h*HD + tc*4 + j] = acc[i][j];
}

// ---------------- host orchestration ----------------------------------------
static inline void run_sgemm_plain(const float* A, const float* W, float* C,
                                   int M, int N, int K) {
    dim3 grid((N + 63) / 64, (M + 63) / 64);
    sgemm_kernel<false,false,false><<<grid, 256>>>(A, W, nullptr, nullptr, C, M, N, K);
}

extern "C" void kernel_launch(void* const* d_in, const int* in_sizes, int n_in,
                              void* d_out, int out_size) {
    (void)in_sizes; (void)n_in; (void)out_size;
    const int*   idx     = (const int*)  d_in[0];
    const float* tok_emb = (const float*)d_in[1];
    const float* pos_emb = (const float*)d_in[2];
    const float* ln1_g   = (const float*)d_in[3];
    const float* ln1_b   = (const float*)d_in[4];
    const float* Wq      = (const float*)d_in[5];
    const float* Wk      = (const float*)d_in[6];
    const float* Wv      = (const float*)d_in[7];
    const float* Wo      = (const float*)d_in[8];
    const float* bo      = (const float*)d_in[9];
    const float* ln2_g   = (const float*)d_in[10];
    const float* ln2_b   = (const float*)d_in[11];
    const float* W1      = (const float*)d_in[12];
    const float* b1      = (const float*)d_in[13];
    const float* W2      = (const float*)d_in[14];
    const float* b2      = (const float*)d_in[15];
    const float* lnf_g   = (const float*)d_in[16];
    const float* lnf_b   = (const float*)d_in[17];
    const float* Wlm     = (const float*)d_in[18];

    float* out    = (float*)d_out;
    float* logits = out;
    float* attn   = out + LOGITS_N;

    float *gx, *gh, *gq, *gk, *gv, *gy, *gu, *gS;
    cudaGetSymbolAddress((void**)&gx, d_x);
    cudaGetSymbolAddress((void**)&gh, d_h);
    cudaGetSymbolAddress((void**)&gq, d_q);
    cudaGetSymbolAddress((void**)&gk, d_k);
    cudaGetSymbolAddress((void**)&gv, d_v);
    cudaGetSymbolAddress((void**)&gy, d_y);
    cudaGetSymbolAddress((void**)&gu, d_u);
    cudaGetSymbolAddress((void**)&gS, d_S);

    embed_kernel<<<BT, 128>>>(idx, tok_emb, pos_emb, gx);

    for (int l = 0; l < LL; l++) {
        const float* wq = Wq + (size_t)l*EE*EE;
        const float* wk = Wk + (size_t)l*EE*EE;
        const float* wv = Wv + (size_t)l*EE*EE;
        const float* wo = Wo + (size_t)l*EE*EE;
        const float* w1 = W1 + (size_t)l*EE*HIDN;
        const float* w2 = W2 + (size_t)l*HIDN*EE;
        float* attn_l = attn + (size_t)l * ATT_PER_L;

        ln_kernel<<<BT, 128>>>(gx, gh, ln1_g + l*EE, ln1_b + l*EE);

        run_sgemm_plain(gh, wq, gq, BT, EE, EE);
        run_sgemm_plain(gh, wk, gk, BT, EE, EE);
        run_sgemm_plain(gh, wv, gv, BT, EE, EE);

        qk_kernel<<<dim3(TT/64, TT/64, BB*HH), 256>>>(gq, gk, gS);
        softmax_kernel<<<BHT, 256>>>(gS, attn_l);
        av_kernel<<<dim3(TT/64, 1, BB*HH), 256>>>(attn_l, gv, gy);

        {   // x = x + y @ Wo + bo
            dim3 grid(EE/64, BT/64);
            sgemm_kernel<false,true,true><<<grid, 256>>>(gy, wo, bo + l*EE, gx, gx, BT, EE, EE);
        }

        ln_kernel<<<BT, 128>>>(gx, gh, ln2_g + l*EE, ln2_b + l*EE);

        {   // u = relu(h @ W1 + b1)
            dim3 grid((HIDN + 63)/64, BT/64);
            sgemm_kernel<true,true,false><<<grid, 256>>>(gh, w1, b1 + l*HIDN, nullptr, gu, BT, HIDN, EE);
        }
        {   // x = x + u @ W2 + b2
            dim3 grid(EE/64, BT/64);
            sgemm_kernel<false,true,true><<<grid, 256>>>(gu, w2, b2 + l*EE, gx, gx, BT, EE, HIDN);
        }
    }

    ln_kernel<<<BT, 128>>>(gx, gh, lnf_g, lnf_b);
    run_sgemm_plain(gh, Wlm, logits, BT, VV, EE);
}

// round 4
// speedup vs baseline: 1.9337x; 1.9337x over previous
#include <cuda_runtime.h>
#include <cuda_bf16.h>
#include <cstdint>
#include <cstddef>

// Problem dims
#define BB 4
#define TT 1024
#define EE 512
#define HH 8
#define LL 4
#define VV 32000
#define HIDN 100
#define HD 64
#define BT (BB*TT)          // 4096
#define BHT (BB*HH*TT)      // 32768
#define QKVS 1536           // packed qkv row stride
#define ATT_PER_L ((size_t)BB*HH*TT*TT)   // 33,554,432
#define LOGITS_N ((size_t)BT*VV)          // 131,072,000

// ---------------- scratch (device globals; no allocations allowed) ----------
__device__ float d_x[BT*EE];
__device__ float d_h[BT*EE];
__device__ float d_qkv[(size_t)BT*QKVS];
__device__ float d_y[BT*EE];
__device__ float d_u[BT*HIDN];
__device__ float d_S[(size_t)BB*HH*TT*TT];     // raw scores, 128 MB
__device__ float d_WlmT[(size_t)VV*EE];        // Wlm^T  [V,E]
__device__ float d_WT[(size_t)LL*4*EE*EE];     // per-layer [qkvT(1536,512); woT(512,512)]

// ======================= tf32 mma.sync GEMM (3xTF32 compensated) =============
// C[M,N] = A[M,K] @ W[K,N], W given TRANSPOSED as BT_[N,K] row-major.
// M%128==0, N%128==0, K%32==0. 256 threads, tile 128x128x32, cp.async 2-stage.
// Each operand is split f = hi + lo (hi = rna-tf32), and we accumulate
// hi*hi + hi*lo + lo*hi -> near-fp32 precision on tensor cores.
#define TILE_F (128*36)           // floats per smem tile (padded rows)
#define GEMM_SMEM (4*TILE_F*4)    // bytes: 2 stages x (A+B)

__device__ __forceinline__ uint32_t smem_u32(const void* p) {
    uint32_t a;
    asm("{ .reg .u64 t; cvta.to.shared.u64 t, %1; cvt.u32.u64 %0, t; }"
        : "=r"(a) : "l"(p));
    return a;
}
__device__ __forceinline__ void cp16(uint32_t saddr, const void* g) {
    asm volatile("cp.async.cg.shared.global [%0], [%1], 16;" :: "r"(saddr), "l"(g));
}
__device__ __forceinline__ uint32_t tf32_hi(float f) {
    uint32_t u;
    asm("cvt.rna.tf32.f32 %0, %1;" : "=r"(u) : "f"(f));
    return u;
}
__device__ __forceinline__ void mma_tf32(float c[4], const uint32_t a[4], const uint32_t b[2]) {
    asm volatile(
        "mma.sync.aligned.m16n8k8.row.col.f32.tf32.tf32.f32 "
        "{%0,%1,%2,%3}, {%4,%5,%6,%7}, {%8,%9}, {%0,%1,%2,%3};"
        : "+f"(c[0]), "+f"(c[1]), "+f"(c[2]), "+f"(c[3])
        : "r"(a[0]), "r"(a[1]), "r"(a[2]), "r"(a[3]), "r"(b[0]), "r"(b[1]));
}

template <bool BIAS, bool RES, bool RELU>
__global__ void __launch_bounds__(256, 2)
mma_gemm(const float* __restrict__ A, const float* __restrict__ BT_,
         const float* __restrict__ bias, const float* __restrict__ res,
         float* __restrict__ C, int M, int N, int K) {
    extern __shared__ float smem_f[];
    float* As = smem_f;                 // [2][TILE_F]
    float* Bs = smem_f + 2*TILE_F;      // [2][TILE_F]

    const int tid = threadIdx.x;
    const int wid = tid >> 5;
    const int lane = tid & 31;
    const int g = lane >> 2, q = lane & 3;
    const int wm = wid & 1, wn = wid >> 1;      // 2 x 4 warp grid

    const int row0 = blockIdx.y * 128;
    const int col0 = blockIdx.x * 128;
    const float* Ap = A + (size_t)row0 * K;
    const float* Bp = BT_ + (size_t)col0 * K;

    const uint32_t sA0 = smem_u32(As);
    const uint32_t sB0 = smem_u32(Bs);

    const int NK = K >> 5;

    // thread's load slots: 4 float4 per tile
    int lrow[4], lc4[4];
    #pragma unroll
    for (int j = 0; j < 4; j++) {
        int i = tid + j * 256;
        lrow[j] = i >> 3;
        lc4[j] = i & 7;
    }

    auto load_stage = [&](int buf, int kt) {
        const int k0 = kt << 5;
        const uint32_t offA = sA0 + buf * TILE_F * 4;
        const uint32_t offB = sB0 + buf * TILE_F * 4;
        #pragma unroll
        for (int j = 0; j < 4; j++) {
            uint32_t so = (uint32_t)(lrow[j] * 36 + lc4[j] * 4) * 4;
            cp16(offA + so, Ap + (size_t)lrow[j] * K + k0 + lc4[j] * 4);
            cp16(offB + so, Bp + (size_t)lrow[j] * K + k0 + lc4[j] * 4);
        }
        asm volatile("cp.async.commit_group;");
    };

    float acc[4][4][4];
    #pragma unroll
    for (int i = 0; i < 4; i++)
        #pragma unroll
        for (int j = 0; j < 4; j++)
            #pragma unroll
            for (int t = 0; t < 4; t++) acc[i][j][t] = 0.0f;

    load_stage(0, 0);

    int buf = 0;
    for (int kt = 0; kt < NK; kt++) {
        if (kt + 1 < NK) {
            load_stage(buf ^ 1, kt + 1);
            asm volatile("cp.async.wait_group 1;");
        } else {
            asm volatile("cp.async.wait_group 0;");
        }
        __syncthreads();

        const float* as = As + buf * TILE_F + (wm * 64 + g) * 36 + q;
        const float* bs = Bs + buf * TILE_F + (wn * 32 + g) * 36 + q;
        #pragma unroll
        for (int s = 0; s < 4; s++) {
            const int k0 = s * 8;
            uint32_t ah[4][4], al[4][4], bh[4][2], bl[4][2];
            #pragma unroll
            for (int i = 0; i < 4; i++) {
                const float* p = as + i * 16 * 36 + k0;
                float f0 = p[0], f1 = p[8 * 36], f2 = p[4], f3 = p[8 * 36 + 4];
                ah[i][0] = tf32_hi(f0);
                ah[i][1] = tf32_hi(f1);
                ah[i][2] = tf32_hi(f2);
                ah[i][3] = tf32_hi(f3);
                al[i][0] = __float_as_uint(f0 - __uint_as_float(ah[i][0]));
                al[i][1] = __float_as_uint(f1 - __uint_as_float(ah[i][1]));
                al[i][2] = __float_as_uint(f2 - __uint_as_float(ah[i][2]));
                al[i][3] = __float_as_uint(f3 - __uint_as_float(ah[i][3]));
            }
            #pragma unroll
            for (int j = 0; j < 4; j++) {
                const float* p = bs + j * 8 * 36 + k0;
                float f0 = p[0], f1 = p[4];
                bh[j][0] = tf32_hi(f0);
                bh[j][1] = tf32_hi(f1);
                bl[j][0] = __float_as_uint(f0 - __uint_as_float(bh[j][0]));
                bl[j][1] = __float_as_uint(f1 - __uint_as_float(bh[j][1]));
            }
            #pragma unroll
            for (int i = 0; i < 4; i++)
                #pragma unroll
                for (int j = 0; j < 4; j++) {
                    mma_tf32(acc[i][j], ah[i], bl[j]);   // hi*lo (small first)
                    mma_tf32(acc[i][j], al[i], bh[j]);   // lo*hi
                    mma_tf32(acc[i][j], ah[i], bh[j]);   // hi*hi
                }
        }
        __syncthreads();
        buf ^= 1;
    }

    // epilogue
    const int m0 = row0 + wm * 64 + g;
    const int n0 = col0 + wn * 32 + 2 * q;
    #pragma unroll
    for (int i = 0; i < 4; i++) {
        #pragma unroll
        for (int j = 0; j < 4; j++) {
            int c = n0 + j * 8;
            float b0 = 0.f, b1 = 0.f;
            if (BIAS) { b0 = bias[c]; b1 = bias[c + 1]; }
            #pragma unroll
            for (int hh = 0; hh < 2; hh++) {
                int r = m0 + i * 16 + hh * 8;
                float v0 = acc[i][j][hh * 2 + 0] + b0;
                float v1 = acc[i][j][hh * 2 + 1] + b1;
                if (RES) {
                    const float* rp = res + (size_t)r * N + c;
                    v0 += rp[0]; v1 += rp[1];
                }
                if (RELU) { v0 = fmaxf(v0, 0.f); v1 = fmaxf(v1, 0.f); }
                float2* cp = (float2*)(C + (size_t)r * N + c);
                *cp = make_float2(v0, v1);
            }
        }
    }
}

// ---------------- transpose W[K,N] -> WT[N,K] --------------------------------
__global__ void transpose_kernel(const float* __restrict__ W, float* __restrict__ WT,
                                 int K, int N) {
    __shared__ float t[32][33];
    int n0 = blockIdx.x * 32, k0 = blockIdx.y * 32;
    int x = threadIdx.x, y = threadIdx.y;   // 32 x 8
    #pragma unroll
    for (int j = 0; j < 32; j += 8)
        t[y + j][x] = W[(size_t)(k0 + y + j) * N + n0 + x];
    __syncthreads();
    #pragma unroll
    for (int j = 0; j < 32; j += 8)
        WT[(size_t)(n0 + y + j) * K + k0 + x] = t[x][y + j];
}

// ---------------- embed: x = tok_emb[idx] + pos_emb -------------------------
__global__ void embed_kernel(const int* __restrict__ idx,
                             const float* __restrict__ tok,
                             const float* __restrict__ pos,
                             float* __restrict__ x) {
    int row = blockIdx.x;
    int t = row & (TT - 1);
    int token = idx[row];
    const float4* tp = (const float4*)(tok + (size_t)token * EE);
    const float4* pp = (const float4*)(pos + (size_t)t * EE);
    float4* xp = (float4*)(x + (size_t)row * EE);
    int c = threadIdx.x;
    float4 a = tp[c], b = pp[c];
    xp[c] = make_float4(a.x + b.x, a.y + b.y, a.z + b.z, a.w + b.w);
}

// ---------------- layernorm --------------------------------------------------
__global__ void ln_kernel(const float* __restrict__ x, float* __restrict__ out,
                          const float* __restrict__ g, const float* __restrict__ b) {
    int row = blockIdx.x;
    int tid = threadIdx.x;
    const float4* xp = (const float4*)(x + (size_t)row * EE);
    float4 v = xp[tid];
    float s = v.x + v.y + v.z + v.w;
    __shared__ float red[4];
    for (int o = 16; o; o >>= 1) s += __shfl_xor_sync(~0u, s, o);
    if ((tid & 31) == 0) red[tid >> 5] = s;
    __syncthreads();
    float mean = (red[0] + red[1] + red[2] + red[3]) / (float)EE;
    float dx = v.x - mean, dy = v.y - mean, dz = v.z - mean, dw = v.w - mean;
    float ss = dx*dx + dy*dy + dz*dz + dw*dw;
    __syncthreads();
    for (int o = 16; o; o >>= 1) ss += __shfl_xor_sync(~0u, ss, o);
    if ((tid & 31) == 0) red[tid >> 5] = ss;
    __syncthreads();
    float var = (red[0] + red[1] + red[2] + red[3]) / (float)EE;
    float inv = 1.0f / sqrtf(var + 1e-5f);
    const float4* gp = (const float4*)g;
    const float4* bp = (const float4*)b;
    float4 gg = gp[tid], bb = bp[tid];
    float4* op = (float4*)(out + (size_t)row * EE);
    op[tid] = make_float4(dx*inv*gg.x + bb.x, dy*inv*gg.y + bb.y,
                          dz*inv*gg.z + bb.z, dw*inv*gg.w + bb.w);
}

// ---------------- SIMT SGEMM (FFN; odd dims) --------------------------------
template <bool RELU, bool BIAS, bool RES>
__global__ void sgemm_kernel(const float* __restrict__ A, const float* __restrict__ W,
                             const float* __restrict__ bias, const float* __restrict__ res,
                             float* __restrict__ C, int M, int N, int K) {
    const int BM = 64, BN = 64, BK = 16;
    __shared__ float As[BK][BM + 1];
    __shared__ float Bs[BK][BN + 1];
    int tid = threadIdx.x;
    int tr = tid >> 4, tc = tid & 15;
    int row0 = blockIdx.y * BM, col0 = blockIdx.x * BN;
    float acc[4][4] = {};
    for (int k0 = 0; k0 < K; k0 += BK) {
        #pragma unroll
        for (int j = 0; j < (BM*BK)/256; j++) {
            int i = tid + j * 256;
            int m = i / BK, kk = i % BK;
            int gr = row0 + m, gk = k0 + kk;
            As[kk][m] = (gr < M && gk < K) ? A[(size_t)gr * K + gk] : 0.0f;
        }
        #pragma unroll
        for (int j = 0; j < (BK*BN)/256; j++) {
            int i = tid + j * 256;
            int kk = i / BN, n = i % BN;
            int gk = k0 + kk, gc = col0 + n;
            Bs[kk][n] = (gk < K && gc < N) ? W[(size_t)gk * N + gc] : 0.0f;
        }
        __syncthreads();
        #pragma unroll
        for (int kk = 0; kk < BK; kk++) {
            float a[4], bv[4];
            #pragma unroll
            for (int i = 0; i < 4; i++) a[i] = As[kk][tr*4 + i];
            #pragma unroll
            for (int j = 0; j < 4; j++) bv[j] = Bs[kk][tc*4 + j];
            #pragma unroll
            for (int i = 0; i < 4; i++)
                #pragma unroll
                for (int j = 0; j < 4; j++)
                    acc[i][j] = fmaf(a[i], bv[j], acc[i][j]);
        }
        __syncthreads();
    }
    #pragma unroll
    for (int i = 0; i < 4; i++) {
        int r = row0 + tr*4 + i;
        if (r >= M) continue;
        #pragma unroll
        for (int j = 0; j < 4; j++) {
            int c = col0 + tc*4 + j;
            if (c >= N) continue;
            float v = acc[i][j];
            if (BIAS) v += bias[c];
            if (RES)  v += res[(size_t)r * N + c];
            if (RELU) v = fmaxf(v, 0.0f);
            C[(size_t)r * N + c] = v;
        }
    }
}

// ---------------- QK^T: S[bh, t, s] = scale * q . k (causal block skip) ------
__global__ void qk_kernel(const float* __restrict__ qkv, float* __restrict__ S) {
    int sb = blockIdx.x, tb = blockIdx.y, bh = blockIdx.z;
    if (sb > tb) return;
    int b = bh >> 3, h = bh & 7;
    const float* qp = qkv + ((size_t)b*TT + tb*64) * QKVS + h*HD;
    const float* kp = qkv + 512 + ((size_t)b*TT + sb*64) * QKVS + h*HD;
    __shared__ float Qs[64][HD + 1];
    __shared__ float Ks[64][HD + 1];
    int tid = threadIdx.x;
    #pragma unroll
    for (int j = 0; j < 16; j++) {
        int i = tid + j * 256;
        int r = i >> 6, d = i & 63;
        Qs[r][d] = qp[(size_t)r * QKVS + d];
        Ks[r][d] = kp[(size_t)r * QKVS + d];
    }
    __syncthreads();
    int tr = tid >> 4, tc = tid & 15;
    float acc[4][4] = {};
    #pragma unroll
    for (int d = 0; d < HD; d++) {
        float a[4], bv[4];
        #pragma unroll
        for (int i = 0; i < 4; i++) a[i] = Qs[tr*4 + i][d];
        #pragma unroll
        for (int j = 0; j < 4; j++) bv[j] = Ks[tc*4 + j][d];
        #pragma unroll
        for (int i = 0; i < 4; i++)
            #pragma unroll
            for (int j = 0; j < 4; j++)
                acc[i][j] = fmaf(a[i], bv[j], acc[i][j]);
    }
    float* sp = S + ((size_t)bh * TT + tb*64) * TT + sb*64;
    #pragma unroll
    for (int i = 0; i < 4; i++)
        #pragma unroll
        for (int j = 0; j < 4; j++)
            sp[(size_t)(tr*4 + i) * TT + tc*4 + j] = acc[i][j] * 0.125f;
}

// ---------------- causal softmax row -> writes attn map into d_out ----------
__global__ void softmax_kernel(const float* __restrict__ S, float* __restrict__ out) {
    int row = blockIdx.x;
    int t = row & (TT - 1);
    const float* sp = S + (size_t)row * TT;
    float* op = out + (size_t)row * TT;
    int tid = threadIdx.x;
    float vals[4];
    float m = -1e30f;
    #pragma unroll
    for (int i = 0; i < 4; i++) {
        int s = tid + i * 256;
        vals[i] = (s <= t) ? sp[s] : -1e30f;
        m = fmaxf(m, vals[i]);
    }
    __shared__ float red[8];
    for (int o = 16; o; o >>= 1) m = fmaxf(m, __shfl_xor_sync(~0u, m, o));
    if ((tid & 31) == 0) red[tid >> 5] = m;
    __syncthreads();
    m = red[0];
    #pragma unroll
    for (int i = 1; i < 8; i++) m = fmaxf(m, red[i]);
    float e[4];
    float ssum = 0.0f;
    #pragma unroll
    for (int i = 0; i < 4; i++) {
        int s = tid + i * 256;
        e[i] = (s <= t) ? expf(vals[i] - m) : 0.0f;
        ssum += e[i];
    }
    __syncthreads();
    for (int o = 16; o; o >>= 1) ssum += __shfl_xor_sync(~0u, ssum, o);
    if ((tid & 31) == 0) red[tid >> 5] = ssum;
    __syncthreads();
    float tot = 0.0f;
    #pragma unroll
    for (int i = 0; i < 8; i++) tot += red[i];
    float inv = 1.0f / tot;
    #pragma unroll
    for (int i = 0; i < 4; i++) {
        int s = tid + i * 256;
        op[s] = e[i] * inv;
    }
}

// ---------------- Y = P @ V (P read back from d_out attn region) ------------
__global__ void av_kernel(const float* __restrict__ P, const float* __restrict__ qkv,
                          float* __restrict__ y) {
    int tb = blockIdx.x, bh = blockIdx.z;
    int b = bh >> 3, h = bh & 7;
    const float* pp = P + ((size_t)bh * TT + tb*64) * TT;
    const float* vbase = qkv + 1024;
    __shared__ float Ps[64][33];
    __shared__ float Vs[32][65];
    int tid = threadIdx.x;
    int tr = tid >> 4, tc = tid & 15;
    float acc[4][4] = {};
    int send = tb*64 + 64;
    for (int s0 = 0; s0 < send; s0 += 32) {
        #pragma unroll
        for (int j = 0; j < 8; j++) {
            int i = tid + j * 256;
            int m = i >> 5, kk = i & 31;
            Ps[m][kk] = pp[(size_t)m * TT + s0 + kk];
        }
        #pragma unroll
        for (int j = 0; j < 8; j++) {
            int i = tid + j * 256;
            int kk = i >> 6, d = i & 63;
            Vs[kk][d] = vbase[((size_t)b*TT + s0 + kk) * QKVS + h*HD + d];
        }
        __syncthreads();
        #pragma unroll
        for (int kk = 0; kk < 32; kk++) {
            float a[4], bv[4];
            #pragma unroll
            for (int i = 0; i < 4; i++) a[i] = Ps[tr*4 + i][kk];
            #pragma unroll
            for (int j = 0; j < 4; j++) bv[j] = Vs[kk][tc*4 + j];
            #pragma unroll
            for (int i = 0; i < 4; i++)
                #pragma unroll
                for (int j = 0; j < 4; j++)
                    acc[i][j] = fmaf(a[i], bv[j], acc[i][j]);
        }
        __syncthreads();
    }
    #pragma unroll
    for (int i = 0; i < 4; i++)
        #pragma unroll
        for (int j = 0; j < 4; j++)
            y[((size_t)b*TT + tb*64 + tr*4 + i) * EE + h*HD + tc*4 + j] = acc[i][j];
}

// ---------------- host orchestration ----------------------------------------
extern "C" void kernel_launch(void* const* d_in, const int* in_sizes, int n_in,
                              void* d_out, int out_size) {
    (void)in_sizes; (void)n_in; (void)out_size;
    const int*   idx     = (const int*)  d_in[0];
    const float* tok_emb = (const float*)d_in[1];
    const float* pos_emb = (const float*)d_in[2];
    const float* ln1_g   = (const float*)d_in[3];
    const float* ln1_b   = (const float*)d_in[4];
    const float* Wq      = (const float*)d_in[5];
    const float* Wk      = (const float*)d_in[6];
    const float* Wv      = (const float*)d_in[7];
    const float* Wo      = (const float*)d_in[8];
    const float* bo      = (const float*)d_in[9];
    const float* ln2_g   = (const float*)d_in[10];
    const float* ln2_b   = (const float*)d_in[11];
    const float* W1      = (const float*)d_in[12];
    const float* b1      = (const float*)d_in[13];
    const float* W2      = (const float*)d_in[14];
    const float* b2      = (const float*)d_in[15];
    const float* lnf_g   = (const float*)d_in[16];
    const float* lnf_b   = (const float*)d_in[17];
    const float* Wlm     = (const float*)d_in[18];

    float* out    = (float*)d_out;
    float* logits = out;
    float* attn   = out + LOGITS_N;

    float *gx, *gh, *gqkv, *gy, *gu, *gS, *gWlmT, *gWT;
    cudaGetSymbolAddress((void**)&gx, d_x);
    cudaGetSymbolAddress((void**)&gh, d_h);
    cudaGetSymbolAddress((void**)&gqkv, d_qkv);
    cudaGetSymbolAddress((void**)&gy, d_y);
    cudaGetSymbolAddress((void**)&gu, d_u);
    cudaGetSymbolAddress((void**)&gS, d_S);
    cudaGetSymbolAddress((void**)&gWlmT, d_WlmT);
    cudaGetSymbolAddress((void**)&gWT, d_WT);

    cudaFuncSetAttribute(mma_gemm<false,false,false>,
                         cudaFuncAttributeMaxDynamicSharedMemorySize, GEMM_SMEM);
    cudaFuncSetAttribute(mma_gemm<true,true,false>,
                         cudaFuncAttributeMaxDynamicSharedMemorySize, GEMM_SMEM);

    // Transpose weights: per layer pack [WqT; WkT; WvT] (1536x512) + WoT (512x512)
    {
        dim3 tb(32, 8);
        for (int l = 0; l < LL; l++) {
            float* base = gWT + (size_t)l * 4 * EE * EE;
            transpose_kernel<<<dim3(EE/32, EE/32), tb>>>(Wq + (size_t)l*EE*EE, base,                 EE, EE);
            transpose_kernel<<<dim3(EE/32, EE/32), tb>>>(Wk + (size_t)l*EE*EE, base + (size_t)512*EE, EE, EE);
            transpose_kernel<<<dim3(EE/32, EE/32), tb>>>(Wv + (size_t)l*EE*EE, base + (size_t)1024*EE, EE, EE);
            transpose_kernel<<<dim3(EE/32, EE/32), tb>>>(Wo + (size_t)l*EE*EE, base + (size_t)1536*EE, EE, EE);
        }
        transpose_kernel<<<dim3(VV/32, EE/32), tb>>>(Wlm, gWlmT, EE, VV);
    }

    embed_kernel<<<BT, 128>>>(idx, tok_emb, pos_emb, gx);

    for (int l = 0; l < LL; l++) {
        float* base = gWT + (size_t)l * 4 * EE * EE;
        const float* qkvT = base;
        const float* woT  = base + (size_t)1536*EE;
        const float* w1 = W1 + (size_t)l*EE*HIDN;
        const float* w2 = W2 + (size_t)l*HIDN*EE;
        float* attn_l = attn + (size_t)l * ATT_PER_L;

        ln_kernel<<<BT, 128>>>(gx, gh, ln1_g + l*EE, ln1_b + l*EE);

        // fused QKV: [4096,1536] = h @ [512,1536]
        mma_gemm<false,false,false><<<dim3(QKVS/128, BT/128), 256, GEMM_SMEM>>>(
            gh, qkvT, nullptr, nullptr, gqkv, BT, QKVS, EE);

        qk_kernel<<<dim3(TT/64, TT/64, BB*HH), 256>>>(gqkv, gS);
        softmax_kernel<<<BHT, 256>>>(gS, attn_l);
        av_kernel<<<dim3(TT/64, 1, BB*HH), 256>>>(attn_l, gqkv, gy);

        // x = x + y @ Wo + bo
        mma_gemm<true,true,false><<<dim3(EE/128, BT/128), 256, GEMM_SMEM>>>(
            gy, woT, bo + l*EE, gx, gx, BT, EE, EE);

        ln_kernel<<<BT, 128>>>(gx, gh, ln2_g + l*EE, ln2_b + l*EE);

        {   // u = relu(h @ W1 + b1)  (N=100, SIMT)
            dim3 grid((HIDN + 63)/64, BT/64);
            sgemm_kernel<true,true,false><<<grid, 256>>>(gh, w1, b1 + l*HIDN, nullptr, gu, BT, HIDN, EE);
        }
        {   // x = x + u @ W2 + b2    (K=100, SIMT)
            dim3 grid(EE/64, BT/64);
            sgemm_kernel<false,true,true><<<grid, 256>>>(gu, w2, b2 + l*EE, gx, gx, BT, EE, HIDN);
        }
    }

    ln_kernel<<<BT, 128>>>(gx, gh, lnf_g, lnf_b);
    mma_gemm<false,false,false><<<dim3(VV/128, BT/128), 256, GEMM_SMEM>>>(
        gh, gWlmT, nullptr, nullptr, logits, BT, VV, EE);
}

// round 6
// speedup vs baseline: 2.2779x; 1.1780x over previous
#include <cuda_runtime.h>
#include <cuda_bf16.h>
#include <cstdint>
#include <cstddef>

// Problem dims
#define BB 4
#define TT 1024
#define EE 512
#define HH 8
#define LL 4
#define VV 32000
#define HIDN 100
#define HD 64
#define BT (BB*TT)          // 4096
#define BHT (BB*HH*TT)      // 32768
#define QKVS 1536           // packed qkv row stride
#define ATT_PER_L ((size_t)BB*HH*TT*TT)   // 33,554,432
#define LOGITS_N ((size_t)BT*VV)          // 131,072,000

// ---------------- scratch (device globals; no allocations allowed) ----------
__device__ float d_x[BT*EE];
__device__ float d_h[BT*EE];
__device__ float d_qkv[(size_t)BT*QKVS];
__device__ float d_y[BT*EE];
__device__ float d_u[BT*HIDN];
__device__ float d_S[(size_t)BB*HH*TT*TT];     // raw scores, 128 MB
__device__ float d_WlmT[(size_t)VV*EE];        // Wlm^T  [V,E]
__device__ float d_WT[(size_t)LL*4*EE*EE];     // per-layer [qkvT(1536,512); woT(512,512)]

// ======================= tf32 mma.sync GEMM (compensated) ====================
// C[M,N] = A[M,K] @ W[K,N], W given TRANSPOSED as BT_[N,K] row-major.
// M%128==0, N%128==0, K%32==0. 256 threads, tile 128x128x32, cp.async 2-stage.
// TERMS==3: hi*hi + hi*lo + lo*hi  (near-fp32)
// TERMS==2: hi*hi + lo*hi          (A split exactly, B tf32-truncated)
#define TILE_F (128*36)           // floats per smem tile (padded rows)
#define GEMM_SMEM (4*TILE_F*4)    // bytes: 2 stages x (A+B)

__device__ __forceinline__ uint32_t smem_u32(const void* p) {
    uint32_t a;
    asm("{ .reg .u64 t; cvta.to.shared.u64 t, %1; cvt.u32.u64 %0, t; }"
        : "=r"(a) : "l"(p));
    return a;
}
__device__ __forceinline__ void cp16(uint32_t saddr, const void* g) {
    asm volatile("cp.async.cg.shared.global [%0], [%1], 16;" :: "r"(saddr), "l"(g));
}
__device__ __forceinline__ uint32_t tf32_hi(float f) {
    uint32_t u;
    asm("cvt.rna.tf32.f32 %0, %1;" : "=r"(u) : "f"(f));
    return u;
}
__device__ __forceinline__ void mma_tf32(float c[4], const uint32_t a[4], const uint32_t b[2]) {
    asm volatile(
        "mma.sync.aligned.m16n8k8.row.col.f32.tf32.tf32.f32 "
        "{%0,%1,%2,%3}, {%4,%5,%6,%7}, {%8,%9}, {%0,%1,%2,%3};"
        : "+f"(c[0]), "+f"(c[1]), "+f"(c[2]), "+f"(c[3])
        : "r"(a[0]), "r"(a[1]), "r"(a[2]), "r"(a[3]), "r"(b[0]), "r"(b[1]));
}

template <bool BIAS, bool RES, bool RELU, int TERMS, bool SWAPG>
__global__ void __launch_bounds__(256, 2)
mma_gemm(const float* __restrict__ A, const float* __restrict__ BT_,
         const float* __restrict__ bias, const float* __restrict__ res,
         float* __restrict__ C, int M, int N, int K) {
    extern __shared__ float smem_f[];
    float* As = smem_f;                 // [2][TILE_F]
    float* Bs = smem_f + 2*TILE_F;      // [2][TILE_F]

    const int tid = threadIdx.x;
    const int wid = tid >> 5;
    const int lane = tid & 31;
    const int g = lane >> 2, q = lane & 3;
    const int wm = wid & 1, wn = wid >> 1;      // 2 x 4 warp grid

    const int row0 = (SWAPG ? blockIdx.x : blockIdx.y) * 128;
    const int col0 = (SWAPG ? blockIdx.y : blockIdx.x) * 128;
    const float* Ap = A + (size_t)row0 * K;
    const float* Bp = BT_ + (size_t)col0 * K;

    const uint32_t sA0 = smem_u32(As);
    const uint32_t sB0 = smem_u32(Bs);

    const int NK = K >> 5;

    // thread's load slots: 4 float4 per tile
    int lrow[4], lc4[4];
    #pragma unroll
    for (int j = 0; j < 4; j++) {
        int i = tid + j * 256;
        lrow[j] = i >> 3;
        lc4[j] = i & 7;
    }

    auto load_stage = [&](int buf, int kt) {
        const int k0 = kt << 5;
        const uint32_t offA = sA0 + buf * TILE_F * 4;
        const uint32_t offB = sB0 + buf * TILE_F * 4;
        #pragma unroll
        for (int j = 0; j < 4; j++) {
            uint32_t so = (uint32_t)(lrow[j] * 36 + lc4[j] * 4) * 4;
            cp16(offA + so, Ap + (size_t)lrow[j] * K + k0 + lc4[j] * 4);
            cp16(offB + so, Bp + (size_t)lrow[j] * K + k0 + lc4[j] * 4);
        }
        asm volatile("cp.async.commit_group;");
    };

    float acc[4][4][4];
    #pragma unroll
    for (int i = 0; i < 4; i++)
        #pragma unroll
        for (int j = 0; j < 4; j++)
            #pragma unroll
            for (int t = 0; t < 4; t++) acc[i][j][t] = 0.0f;

    load_stage(0, 0);

    int buf = 0;
    for (int kt = 0; kt < NK; kt++) {
        if (kt + 1 < NK) {
            load_stage(buf ^ 1, kt + 1);
            asm volatile("cp.async.wait_group 1;");
        } else {
            asm volatile("cp.async.wait_group 0;");
        }
        __syncthreads();

        const float* as = As + buf * TILE_F + (wm * 64 + g) * 36 + q;
        const float* bs = Bs + buf * TILE_F + (wn * 32 + g) * 36 + q;
        #pragma unroll
        for (int s = 0; s < 4; s++) {
            const int k0 = s * 8;
            uint32_t ah[4][4], al[4][4], bh[4][2], bl[4][2];
            #pragma unroll
            for (int i = 0; i < 4; i++) {
                const float* p = as + i * 16 * 36 + k0;
                float f0 = p[0], f1 = p[8 * 36], f2 = p[4], f3 = p[8 * 36 + 4];
                ah[i][0] = tf32_hi(f0);
                ah[i][1] = tf32_hi(f1);
                ah[i][2] = tf32_hi(f2);
                ah[i][3] = tf32_hi(f3);
                al[i][0] = __float_as_uint(f0 - __uint_as_float(ah[i][0]));
                al[i][1] = __float_as_uint(f1 - __uint_as_float(ah[i][1]));
                al[i][2] = __float_as_uint(f2 - __uint_as_float(ah[i][2]));
                al[i][3] = __float_as_uint(f3 - __uint_as_float(ah[i][3]));
            }
            #pragma unroll
            for (int j = 0; j < 4; j++) {
                const float* p = bs + j * 8 * 36 + k0;
                float f0 = p[0], f1 = p[4];
                bh[j][0] = tf32_hi(f0);
                bh[j][1] = tf32_hi(f1);
                if (TERMS >= 3) {
                    bl[j][0] = __float_as_uint(f0 - __uint_as_float(bh[j][0]));
                    bl[j][1] = __float_as_uint(f1 - __uint_as_float(bh[j][1]));
                }
            }
            #pragma unroll
            for (int i = 0; i < 4; i++)
                #pragma unroll
                for (int j = 0; j < 4; j++) {
                    if (TERMS >= 3) mma_tf32(acc[i][j], ah[i], bl[j]);  // hi*lo
                    mma_tf32(acc[i][j], al[i], bh[j]);                  // lo*hi
                    mma_tf32(acc[i][j], ah[i], bh[j]);                  // hi*hi
                }
        }
        __syncthreads();
        buf ^= 1;
    }

    // epilogue
    const int m0 = row0 + wm * 64 + g;
    const int n0 = col0 + wn * 32 + 2 * q;
    #pragma unroll
    for (int i = 0; i < 4; i++) {
        #pragma unroll
        for (int j = 0; j < 4; j++) {
            int c = n0 + j * 8;
            float b0 = 0.f, b1 = 0.f;
            if (BIAS) { b0 = bias[c]; b1 = bias[c + 1]; }
            #pragma unroll
            for (int hh = 0; hh < 2; hh++) {
                int r = m0 + i * 16 + hh * 8;
                float v0 = acc[i][j][hh * 2 + 0] + b0;
                float v1 = acc[i][j][hh * 2 + 1] + b1;
                if (RES) {
                    const float* rp = res + (size_t)r * N + c;
                    v0 += rp[0]; v1 += rp[1];
                }
                if (RELU) { v0 = fmaxf(v0, 0.f); v1 = fmaxf(v1, 0.f); }
                float2* cp = (float2*)(C + (size_t)r * N + c);
                *cp = make_float2(v0, v1);
            }
        }
    }
}

// ---------------- transpose W[K,N] -> WT[N,K] --------------------------------
__global__ void transpose_kernel(const float* __restrict__ W, float* __restrict__ WT,
                                 int K, int N) {
    __shared__ float t[32][33];
    int n0 = blockIdx.x * 32, k0 = blockIdx.y * 32;
    int x = threadIdx.x, y = threadIdx.y;   // 32 x 8
    #pragma unroll
    for (int j = 0; j < 32; j += 8)
        t[y + j][x] = W[(size_t)(k0 + y + j) * N + n0 + x];
    __syncthreads();
    #pragma unroll
    for (int j = 0; j < 32; j += 8)
        WT[(size_t)(n0 + y + j) * K + k0 + x] = t[x][y + j];
}

// ---------------- embed: x = tok_emb[idx] + pos_emb -------------------------
__global__ void embed_kernel(const int* __restrict__ idx,
                             const float* __restrict__ tok,
                             const float* __restrict__ pos,
                             float* __restrict__ x) {
    int row = blockIdx.x;
    int t = row & (TT - 1);
    int token = idx[row];
    const float4* tp = (const float4*)(tok + (size_t)token * EE);
    const float4* pp = (const float4*)(pos + (size_t)t * EE);
    float4* xp = (float4*)(x + (size_t)row * EE);
    int c = threadIdx.x;
    float4 a = tp[c], b = pp[c];
    xp[c] = make_float4(a.x + b.x, a.y + b.y, a.z + b.z, a.w + b.w);
}

// ---------------- layernorm --------------------------------------------------
__global__ void ln_kernel(const float* __restrict__ x, float* __restrict__ out,
                          const float* __restrict__ g, const float* __restrict__ b) {
    int row = blockIdx.x;
    int tid = threadIdx.x;
    const float4* xp = (const float4*)(x + (size_t)row * EE);
    float4 v = xp[tid];
    float s = v.x + v.y + v.z + v.w;
    __shared__ float red[4];
    for (int o = 16; o; o >>= 1) s += __shfl_xor_sync(~0u, s, o);
    if ((tid & 31) == 0) red[tid >> 5] = s;
    __syncthreads();
    float mean = (red[0] + red[1] + red[2] + red[3]) / (float)EE;
    float dx = v.x - mean, dy = v.y - mean, dz = v.z - mean, dw = v.w - mean;
    float ss = dx*dx + dy*dy + dz*dz + dw*dw;
    __syncthreads();
    for (int o = 16; o; o >>= 1) ss += __shfl_xor_sync(~0u, ss, o);
    if ((tid & 31) == 0) red[tid >> 5] = ss;
    __syncthreads();
    float var = (red[0] + red[1] + red[2] + red[3]) / (float)EE;
    float inv = 1.0f / sqrtf(var + 1e-5f);
    const float4* gp = (const float4*)g;
    const float4* bp = (const float4*)b;
    float4 gg = gp[tid], bb = bp[tid];
    float4* op = (float4*)(out + (size_t)row * EE);
    op[tid] = make_float4(dx*inv*gg.x + bb.x, dy*inv*gg.y + bb.y,
                          dz*inv*gg.z + bb.z, dw*inv*gg.w + bb.w);
}

// ---------------- SIMT SGEMM (FFN; odd dims) --------------------------------
template <bool RELU, bool BIAS, bool RES>
__global__ void sgemm_kernel(const float* __restrict__ A, const float* __restrict__ W,
                             const float* __restrict__ bias, const float* __restrict__ res,
                             float* __restrict__ C, int M, int N, int K) {
    const int BM = 64, BN = 64, BK = 16;
    __shared__ float As[BK][BM + 1];
    __shared__ float Bs[BK][BN + 1];
    int tid = threadIdx.x;
    int tr = tid >> 4, tc = tid & 15;
    int row0 = blockIdx.y * BM, col0 = blockIdx.x * BN;
    float acc[4][4] = {};
    for (int k0 = 0; k0 < K; k0 += BK) {
        #pragma unroll
        for (int j = 0; j < (BM*BK)/256; j++) {
            int i = tid + j * 256;
            int m = i / BK, kk = i % BK;
            int gr = row0 + m, gk = k0 + kk;
            As[kk][m] = (gr < M && gk < K) ? A[(size_t)gr * K + gk] : 0.0f;
        }
        #pragma unroll
        for (int j = 0; j < (BK*BN)/256; j++) {
            int i = tid + j * 256;
            int kk = i / BN, n = i % BN;
            int gk = k0 + kk, gc = col0 + n;
            Bs[kk][n] = (gk < K && gc < N) ? W[(size_t)gk * N + gc] : 0.0f;
        }
        __syncthreads();
        #pragma unroll
        for (int kk = 0; kk < BK; kk++) {
            float a[4], bv[4];
            #pragma unroll
            for (int i = 0; i < 4; i++) a[i] = As[kk][tr*4 + i];
            #pragma unroll
            for (int j = 0; j < 4; j++) bv[j] = Bs[kk][tc*4 + j];
            #pragma unroll
            for (int i = 0; i < 4; i++)
                #pragma unroll
                for (int j = 0; j < 4; j++)
                    acc[i][j] = fmaf(a[i], bv[j], acc[i][j]);
        }
        __syncthreads();
    }
    #pragma unroll
    for (int i = 0; i < 4; i++) {
        int r = row0 + tr*4 + i;
        if (r >= M) continue;
        #pragma unroll
        for (int j = 0; j < 4; j++) {
            int c = col0 + tc*4 + j;
            if (c >= N) continue;
            float v = acc[i][j];
            if (BIAS) v += bias[c];
            if (RES)  v += res[(size_t)r * N + c];
            if (RELU) v = fmaxf(v, 0.0f);
            C[(size_t)r * N + c] = v;
        }
    }
}

// ---------------- QK^T: S[bh, t, s] = scale * q . k (causal block skip) ------
__global__ void qk_kernel(const float* __restrict__ qkv, float* __restrict__ S) {
    int sb = blockIdx.x, tb = blockIdx.y, bh = blockIdx.z;
    if (sb > tb) return;
    int b = bh >> 3, h = bh & 7;
    const float* qp = qkv + ((size_t)b*TT + tb*64) * QKVS + h*HD;
    const float* kp = qkv + 512 + ((size_t)b*TT + sb*64) * QKVS + h*HD;
    __shared__ float Qs[64][HD + 1];
    __shared__ float Ks[64][HD + 1];
    int tid = threadIdx.x;
    #pragma unroll
    for (int j = 0; j < 16; j++) {
        int i = tid + j * 256;
        int r = i >> 6, d = i & 63;
        Qs[r][d] = qp[(size_t)r * QKVS + d];
        Ks[r][d] = kp[(size_t)r * QKVS + d];
    }
    __syncthreads();
    int tr = tid >> 4, tc = tid & 15;
    float acc[4][4] = {};
    #pragma unroll
    for (int d = 0; d < HD; d++) {
        float a[4], bv[4];
        #pragma unroll
        for (int i = 0; i < 4; i++) a[i] = Qs[tr*4 + i][d];
        #pragma unroll
        for (int j = 0; j < 4; j++) bv[j] = Ks[tc*4 + j][d];
        #pragma unroll
        for (int i = 0; i < 4; i++)
            #pragma unroll
            for (int j = 0; j < 4; j++)
                acc[i][j] = fmaf(a[i], bv[j], acc[i][j]);
    }
    float* sp = S + ((size_t)bh * TT + tb*64) * TT + sb*64;
    #pragma unroll
    for (int i = 0; i < 4; i++)
        #pragma unroll
        for (int j = 0; j < 4; j++)
            sp[(size_t)(tr*4 + i) * TT + tc*4 + j] = acc[i][j] * 0.125f;
}

// ---------------- causal softmax row -> writes attn map into d_out ----------
__global__ void softmax_kernel(const float* __restrict__ S, float* __restrict__ out) {
    int row = blockIdx.x;
    int t = row & (TT - 1);
    const float* sp = S + (size_t)row * TT;
    float* op = out + (size_t)row * TT;
    int tid = threadIdx.x;
    float vals[4];
    float m = -1e30f;
    #pragma unroll
    for (int i = 0; i < 4; i++) {
        int s = tid + i * 256;
        vals[i] = (s <= t) ? sp[s] : -1e30f;
        m = fmaxf(m, vals[i]);
    }
    __shared__ float red[8];
    for (int o = 16; o; o >>= 1) m = fmaxf(m, __shfl_xor_sync(~0u, m, o));
    if ((tid & 31) == 0) red[tid >> 5] = m;
    __syncthreads();
    m = red[0];
    #pragma unroll
    for (int i = 1; i < 8; i++) m = fmaxf(m, red[i]);
    float e[4];
    float ssum = 0.0f;
    #pragma unroll
    for (int i = 0; i < 4; i++) {
        int s = tid + i * 256;
        e[i] = (s <= t) ? expf(vals[i] - m) : 0.0f;
        ssum += e[i];
    }
    __syncthreads();
    for (int o = 16; o; o >>= 1) ssum += __shfl_xor_sync(~0u, ssum, o);
    if ((tid & 31) == 0) red[tid >> 5] = ssum;
    __syncthreads();
    float tot = 0.0f;
    #pragma unroll
    for (int i = 0; i < 8; i++) tot += red[i];
    float inv = 1.0f / tot;
    #pragma unroll
    for (int i = 0; i < 4; i++) {
        int s = tid + i * 256;
        op[s] = e[i] * inv;
    }
}

// ---------------- Y = P @ V (P read back from d_out attn region) ------------
__global__ void av_kernel(const float* __restrict__ P, const float* __restrict__ qkv,
                          float* __restrict__ y) {
    int tb = blockIdx.x, bh = blockIdx.z;
    int b = bh >> 3, h = bh & 7;
    const float* pp = P + ((size_t)bh * TT + tb*64) * TT;
    const float* vbase = qkv + 1024;
    __shared__ float Ps[64][33];
    __shared__ float Vs[32][65];
    int tid = threadIdx.x;
    int tr = tid >> 4, tc = tid & 15;
    float acc[4][4] = {};
    int send = tb*64 + 64;
    for (int s0 = 0; s0 < send; s0 += 32) {
        #pragma unroll
        for (int j = 0; j < 8; j++) {
            int i = tid + j * 256;
            int m = i >> 5, kk = i & 31;
            Ps[m][kk] = pp[(size_t)m * TT + s0 + kk];
        }
        #pragma unroll
        for (int j = 0; j < 8; j++) {
            int i = tid + j * 256;
            int kk = i >> 6, d = i & 63;
            Vs[kk][d] = vbase[((size_t)b*TT + s0 + kk) * QKVS + h*HD + d];
        }
        __syncthreads();
        #pragma unroll
        for (int kk = 0; kk < 32; kk++) {
            float a[4], bv[4];
            #pragma unroll
            for (int i = 0; i < 4; i++) a[i] = Ps[tr*4 + i][kk];
            #pragma unroll
            for (int j = 0; j < 4; j++) bv[j] = Vs[kk][tc*4 + j];
            #pragma unroll
            for (int i = 0; i < 4; i++)
                #pragma unroll
                for (int j = 0; j < 4; j++)
                    acc[i][j] = fmaf(a[i], bv[j], acc[i][j]);
        }
        __syncthreads();
    }
    #pragma unroll
    for (int i = 0; i < 4; i++)
        #pragma unroll
        for (int j = 0; j < 4; j++)
            y[((size_t)b*TT + tb*64 + tr*4 + i) * EE + h*HD + tc*4 + j] = acc[i][j];
}

// ---------------- host orchestration ----------------------------------------
extern "C" void kernel_launch(void* const* d_in, const int* in_sizes, int n_in,
                              void* d_out, int out_size) {
    (void)in_sizes; (void)n_in; (void)out_size;
    const int*   idx     = (const int*)  d_in[0];
    const float* tok_emb = (const float*)d_in[1];
    const float* pos_emb = (const float*)d_in[2];
    const float* ln1_g   = (const float*)d_in[3];
    const float* ln1_b   = (const float*)d_in[4];
    const float* Wq      = (const float*)d_in[5];
    const float* Wk      = (const float*)d_in[6];
    const float* Wv      = (const float*)d_in[7];
    const float* Wo      = (const float*)d_in[8];
    const float* bo      = (const float*)d_in[9];
    const float* ln2_g   = (const float*)d_in[10];
    const float* ln2_b   = (const float*)d_in[11];
    const float* W1      = (const float*)d_in[12];
    const float* b1      = (const float*)d_in[13];
    const float* W2      = (const float*)d_in[14];
    const float* b2      = (const float*)d_in[15];
    const float* lnf_g   = (const float*)d_in[16];
    const float* lnf_b   = (const float*)d_in[17];
    const float* Wlm     = (const float*)d_in[18];

    float* out    = (float*)d_out;
    float* logits = out;
    float* attn   = out + LOGITS_N;

    float *gx, *gh, *gqkv, *gy, *gu, *gS, *gWlmT, *gWT;
    cudaGetSymbolAddress((void**)&gx, d_x);
    cudaGetSymbolAddress((void**)&gh, d_h);
    cudaGetSymbolAddress((void**)&gqkv, d_qkv);
    cudaGetSymbolAddress((void**)&gy, d_y);
    cudaGetSymbolAddress((void**)&gu, d_u);
    cudaGetSymbolAddress((void**)&gS, d_S);
    cudaGetSymbolAddress((void**)&gWlmT, d_WlmT);
    cudaGetSymbolAddress((void**)&gWT, d_WT);

    cudaFuncSetAttribute(mma_gemm<false,false,false,3,false>,
                         cudaFuncAttributeMaxDynamicSharedMemorySize, GEMM_SMEM);
    cudaFuncSetAttribute(mma_gemm<true,true,false,3,false>,
                         cudaFuncAttributeMaxDynamicSharedMemorySize, GEMM_SMEM);
    cudaFuncSetAttribute(mma_gemm<false,false,false,2,true>,
                         cudaFuncAttributeMaxDynamicSharedMemorySize, GEMM_SMEM);

    // Transpose weights: per layer pack [WqT; WkT; WvT] (1536x512) + WoT (512x512)
    {
        dim3 tb(32, 8);
        for (int l = 0; l < LL; l++) {
            float* base = gWT + (size_t)l * 4 * EE * EE;
            transpose_kernel<<<dim3(EE/32, EE/32), tb>>>(Wq + (size_t)l*EE*EE, base,                 EE, EE);
            transpose_kernel<<<dim3(EE/32, EE/32), tb>>>(Wk + (size_t)l*EE*EE, base + (size_t)512*EE, EE, EE);
            transpose_kernel<<<dim3(EE/32, EE/32), tb>>>(Wv + (size_t)l*EE*EE, base + (size_t)1024*EE, EE, EE);
            transpose_kernel<<<dim3(EE/32, EE/32), tb>>>(Wo + (size_t)l*EE*EE, base + (size_t)1536*EE, EE, EE);
        }
        transpose_kernel<<<dim3(VV/32, EE/32), tb>>>(Wlm, gWlmT, EE, VV);
    }

    embed_kernel<<<BT, 128>>>(idx, tok_emb, pos_emb, gx);

    for (int l = 0; l < LL; l++) {
        float* base = gWT + (size_t)l * 4 * EE * EE;
        const float* qkvT = base;
        const float* woT  = base + (size_t)1536*EE;
        const float* w1 = W1 + (size_t)l*EE*HIDN;
        const float* w2 = W2 + (size_t)l*HIDN*EE;
        float* attn_l = attn + (size_t)l * ATT_PER_L;

        ln_kernel<<<BT, 128>>>(gx, gh, ln1_g + l*EE, ln1_b + l*EE);

        // fused QKV: [4096,1536] = h @ [512,1536]
        mma_gemm<false,false,false,3,false><<<dim3(QKVS/128, BT/128), 256, GEMM_SMEM>>>(
            gh, qkvT, nullptr, nullptr, gqkv, BT, QKVS, EE);

        qk_kernel<<<dim3(TT/64, TT/64, BB*HH), 256>>>(gqkv, gS);
        softmax_kernel<<<BHT, 256>>>(gS, attn_l);
        av_kernel<<<dim3(TT/64, 1, BB*HH), 256>>>(attn_l, gqkv, gy);

        // x = x + y @ Wo + bo
        mma_gemm<true,true,false,3,false><<<dim3(EE/128, BT/128), 256, GEMM_SMEM>>>(
            gy, woT, bo + l*EE, gx, gx, BT, EE, EE);

        ln_kernel<<<BT, 128>>>(gx, gh, ln2_g + l*EE, ln2_b + l*EE);

        {   // u = relu(h @ W1 + b1)  (N=100, SIMT)
            dim3 grid((HIDN + 63)/64, BT/64);
            sgemm_kernel<true,true,false><<<grid, 256>>>(gh, w1, b1 + l*HIDN, nullptr, gu, BT, HIDN, EE);
        }
        {   // x = x + u @ W2 + b2    (K=100, SIMT)
            dim3 grid(EE/64, BT/64);
            sgemm_kernel<false,true,true><<<grid, 256>>>(gu, w2, b2 + l*EE, gx, gx, BT, EE, HIDN);
        }
    }

    ln_kernel<<<BT, 128>>>(gx, gh, lnf_g, lnf_b);
    // logits: 2-term compensation (A split, W truncated) + M-fastest grid for
    // L2-friendly weight streaming (wave = all 32 M-blocks x ~9 N-blocks).
    mma_gemm<false,false,false,2,true><<<dim3(BT/128, VV/128), 256, GEMM_SMEM>>>(
        gh, gWlmT, nullptr, nullptr, logits, BT, VV, EE);
}

// round 7
// speedup vs baseline: 2.5029x; 1.0988x over previous
#include <cuda_runtime.h>
#include <cuda_bf16.h>
#include <cstdint>
#include <cstddef>

// Problem dims
#define BB 4
#define TT 1024
#define EE 512
#define HH 8
#define LL 4
#define VV 32000
#define HIDN 100
#define HD 64
#define BT (BB*TT)          // 4096
#define BHT (BB*HH*TT)      // 32768
#define QKVS 1536           // packed qkv row stride
#define ATT_PER_L ((size_t)BB*HH*TT*TT)   // 33,554,432
#define LOGITS_N ((size_t)BT*VV)          // 131,072,000

// ---------------- scratch (device globals; no allocations allowed) ----------
__device__ float d_x[BT*EE];
__device__ float d_h[BT*EE];
__device__ float d_qkv[(size_t)BT*QKVS];
__device__ float d_y[BT*EE];
__device__ float d_u[BT*HIDN];
__device__ float d_S[(size_t)BB*HH*TT*TT];     // raw scores, 128 MB
__device__ float d_WlmT[(size_t)VV*EE];        // Wlm^T  [V,E]
__device__ float d_WT[(size_t)LL*4*EE*EE];     // per-layer [qkvT(1536,512); woT(512,512)]

// ======================= bf16 mma.sync GEMM (3-term compensated) =============
// C[M,N] = A[M,K] @ W[K,N], W given TRANSPOSED as BT_[N,K] row-major.
// M%128==0, N%128==0, K%32==0. 256 threads, tile 128x128x32, cp.async 2-stage.
// Each fp32 operand f = hi + lo with hi = rn-bf16(f), lo = bf16(f - hi).
// Accumulate ah*bh + ah*bl + al*bh in fp32 (drops only ~2^-16 lolo term).
#define TILE_F (128*36)           // floats per smem tile (padded rows)
#define GEMM_SMEM (4*TILE_F*4)    // bytes: 2 stages x (A+B)

__device__ __forceinline__ uint32_t smem_u32(const void* p) {
    uint32_t a;
    asm("{ .reg .u64 t; cvta.to.shared.u64 t, %1; cvt.u32.u64 %0, t; }"
        : "=r"(a) : "l"(p));
    return a;
}
__device__ __forceinline__ void cp16(uint32_t saddr, const void* g) {
    asm volatile("cp.async.cg.shared.global [%0], [%1], 16;" :: "r"(saddr), "l"(g));
}
// pack two fp32 into bf16x2: low16 = bf16(f0), high16 = bf16(f1)
__device__ __forceinline__ uint32_t pack2_hi(float f0, float f1) {
    uint32_t r;
    asm("cvt.rn.bf16x2.f32 %0, %1, %2;" : "=r"(r) : "f"(f1), "f"(f0));
    return r;
}
// residual pack: bf16x2 of (f - hi)
__device__ __forceinline__ uint32_t pack2_lo(float f0, float f1, uint32_t hi) {
    float h0 = __uint_as_float(hi << 16);
    float h1 = __uint_as_float(hi & 0xffff0000u);
    uint32_t r;
    asm("cvt.rn.bf16x2.f32 %0, %1, %2;" : "=r"(r) : "f"(f1 - h1), "f"(f0 - h0));
    return r;
}
__device__ __forceinline__ void mma_bf16(float c[4], const uint32_t a[4], const uint32_t b[2]) {
    asm volatile(
        "mma.sync.aligned.m16n8k16.row.col.f32.bf16.bf16.f32 "
        "{%0,%1,%2,%3}, {%4,%5,%6,%7}, {%8,%9}, {%0,%1,%2,%3};"
        : "+f"(c[0]), "+f"(c[1]), "+f"(c[2]), "+f"(c[3])
        : "r"(a[0]), "r"(a[1]), "r"(a[2]), "r"(a[3]), "r"(b[0]), "r"(b[1]));
}

template <bool BIAS, bool RES, bool RELU, bool SWAPG>
__global__ void __launch_bounds__(256, 2)
mma_gemm(const float* __restrict__ A, const float* __restrict__ BT_,
         const float* __restrict__ bias, const float* __restrict__ res,
         float* __restrict__ C, int M, int N, int K) {
    extern __shared__ float smem_f[];
    float* As = smem_f;                 // [2][TILE_F]
    float* Bs = smem_f + 2*TILE_F;      // [2][TILE_F]

    const int tid = threadIdx.x;
    const int wid = tid >> 5;
    const int lane = tid & 31;
    const int g = lane >> 2, q = lane & 3;
    const int wm = wid & 1, wn = wid >> 1;      // 2 x 4 warp grid

    const int row0 = (SWAPG ? blockIdx.x : blockIdx.y) * 128;
    const int col0 = (SWAPG ? blockIdx.y : blockIdx.x) * 128;
    const float* Ap = A + (size_t)row0 * K;
    const float* Bp = BT_ + (size_t)col0 * K;

    const uint32_t sA0 = smem_u32(As);
    const uint32_t sB0 = smem_u32(Bs);

    const int NK = K >> 5;

    // thread's load slots: 4 float4 per tile
    int lrow[4], lc4[4];
    #pragma unroll
    for (int j = 0; j < 4; j++) {
        int i = tid + j * 256;
        lrow[j] = i >> 3;
        lc4[j] = i & 7;
    }

    auto load_stage = [&](int buf, int kt) {
        const int k0 = kt << 5;
        const uint32_t offA = sA0 + buf * TILE_F * 4;
        const uint32_t offB = sB0 + buf * TILE_F * 4;
        #pragma unroll
        for (int j = 0; j < 4; j++) {
            uint32_t so = (uint32_t)(lrow[j] * 36 + lc4[j] * 4) * 4;
            cp16(offA + so, Ap + (size_t)lrow[j] * K + k0 + lc4[j] * 4);
            cp16(offB + so, Bp + (size_t)lrow[j] * K + k0 + lc4[j] * 4);
        }
        asm volatile("cp.async.commit_group;");
    };

    float acc[4][4][4];
    #pragma unroll
    for (int i = 0; i < 4; i++)
        #pragma unroll
        for (int j = 0; j < 4; j++)
            #pragma unroll
            for (int t = 0; t < 4; t++) acc[i][j][t] = 0.0f;

    load_stage(0, 0);

    int buf = 0;
    for (int kt = 0; kt < NK; kt++) {
        if (kt + 1 < NK) {
            load_stage(buf ^ 1, kt + 1);
            asm volatile("cp.async.wait_group 1;");
        } else {
            asm volatile("cp.async.wait_group 0;");
        }
        __syncthreads();

        // fragment base pointers (k offset 2q for k16 fragments)
        const float* as = As + buf * TILE_F + (wm * 64 + g) * 36 + 2 * q;
        const float* bs = Bs + buf * TILE_F + (wn * 32 + g) * 36 + 2 * q;
        #pragma unroll
        for (int s = 0; s < 2; s++) {          // two k16 steps per 32-chunk
            const int k0 = s * 16;
            uint32_t ah[4][4], al[4][4], bh[4][2], bl[4][2];
            #pragma unroll
            for (int i = 0; i < 4; i++) {
                const float* p = as + i * 16 * 36 + k0;
                float2 x0 = *(const float2*)(p);                 // row g,   k 2q..2q+1
                float2 x1 = *(const float2*)(p + 8 * 36);        // row g+8, k 2q..2q+1
                float2 x2 = *(const float2*)(p + 8);             // row g,   k 2q+8..9
                float2 x3 = *(const float2*)(p + 8 * 36 + 8);    // row g+8, k 2q+8..9
                ah[i][0] = pack2_hi(x0.x, x0.y); al[i][0] = pack2_lo(x0.x, x0.y, ah[i][0]);
                ah[i][1] = pack2_hi(x1.x, x1.y); al[i][1] = pack2_lo(x1.x, x1.y, ah[i][1]);
                ah[i][2] = pack2_hi(x2.x, x2.y); al[i][2] = pack2_lo(x2.x, x2.y, ah[i][2]);
                ah[i][3] = pack2_hi(x3.x, x3.y); al[i][3] = pack2_lo(x3.x, x3.y, ah[i][3]);
            }
            #pragma unroll
            for (int j = 0; j < 4; j++) {
                const float* p = bs + j * 8 * 36 + k0;
                float2 y0 = *(const float2*)(p);                 // col g, k 2q..2q+1
                float2 y1 = *(const float2*)(p + 8);             // col g, k 2q+8..9
                bh[j][0] = pack2_hi(y0.x, y0.y); bl[j][0] = pack2_lo(y0.x, y0.y, bh[j][0]);
                bh[j][1] = pack2_hi(y1.x, y1.y); bl[j][1] = pack2_lo(y1.x, y1.y, bh[j][1]);
            }
            #pragma unroll
            for (int i = 0; i < 4; i++)
                #pragma unroll
                for (int j = 0; j < 4; j++) {
                    mma_bf16(acc[i][j], ah[i], bl[j]);   // hi*lo
                    mma_bf16(acc[i][j], al[i], bh[j]);   // lo*hi
                    mma_bf16(acc[i][j], ah[i], bh[j]);   // hi*hi
                }
        }
        __syncthreads();
        buf ^= 1;
    }

    // epilogue (m16n8k16 acc layout == m16n8k8: c0,c1 row g; c2,c3 row g+8)
    const int m0 = row0 + wm * 64 + g;
    const int n0 = col0 + wn * 32 + 2 * q;
    #pragma unroll
    for (int i = 0; i < 4; i++) {
        #pragma unroll
        for (int j = 0; j < 4; j++) {
            int c = n0 + j * 8;
            float b0 = 0.f, b1 = 0.f;
            if (BIAS) { b0 = bias[c]; b1 = bias[c + 1]; }
            #pragma unroll
            for (int hh = 0; hh < 2; hh++) {
                int r = m0 + i * 16 + hh * 8;
                float v0 = acc[i][j][hh * 2 + 0] + b0;
                float v1 = acc[i][j][hh * 2 + 1] + b1;
                if (RES) {
                    const float* rp = res + (size_t)r * N + c;
                    v0 += rp[0]; v1 += rp[1];
                }
                if (RELU) { v0 = fmaxf(v0, 0.f); v1 = fmaxf(v1, 0.f); }
                float2* cp = (float2*)(C + (size_t)r * N + c);
                *cp = make_float2(v0, v1);
            }
        }
    }
}

// ---------------- transpose W[K,N] -> WT[N,K] --------------------------------
__global__ void transpose_kernel(const float* __restrict__ W, float* __restrict__ WT,
                                 int K, int N) {
    __shared__ float t[32][33];
    int n0 = blockIdx.x * 32, k0 = blockIdx.y * 32;
    int x = threadIdx.x, y = threadIdx.y;   // 32 x 8
    #pragma unroll
    for (int j = 0; j < 32; j += 8)
        t[y + j][x] = W[(size_t)(k0 + y + j) * N + n0 + x];
    __syncthreads();
    #pragma unroll
    for (int j = 0; j < 32; j += 8)
        WT[(size_t)(n0 + y + j) * K + k0 + x] = t[x][y + j];
}

// ---------------- embed: x = tok_emb[idx] + pos_emb -------------------------
__global__ void embed_kernel(const int* __restrict__ idx,
                             const float* __restrict__ tok,
                             const float* __restrict__ pos,
                             float* __restrict__ x) {
    int row = blockIdx.x;
    int t = row & (TT - 1);
    int token = idx[row];
    const float4* tp = (const float4*)(tok + (size_t)token * EE);
    const float4* pp = (const float4*)(pos + (size_t)t * EE);
    float4* xp = (float4*)(x + (size_t)row * EE);
    int c = threadIdx.x;
    float4 a = tp[c], b = pp[c];
    xp[c] = make_float4(a.x + b.x, a.y + b.y, a.z + b.z, a.w + b.w);
}

// ---------------- layernorm --------------------------------------------------
__global__ void ln_kernel(const float* __restrict__ x, float* __restrict__ out,
                          const float* __restrict__ g, const float* __restrict__ b) {
    int row = blockIdx.x;
    int tid = threadIdx.x;
    const float4* xp = (const float4*)(x + (size_t)row * EE);
    float4 v = xp[tid];
    float s = v.x + v.y + v.z + v.w;
    __shared__ float red[4];
    for (int o = 16; o; o >>= 1) s += __shfl_xor_sync(~0u, s, o);
    if ((tid & 31) == 0) red[tid >> 5] = s;
    __syncthreads();
    float mean = (red[0] + red[1] + red[2] + red[3]) / (float)EE;
    float dx = v.x - mean, dy = v.y - mean, dz = v.z - mean, dw = v.w - mean;
    float ss = dx*dx + dy*dy + dz*dz + dw*dw;
    __syncthreads();
    for (int o = 16; o; o >>= 1) ss += __shfl_xor_sync(~0u, ss, o);
    if ((tid & 31) == 0) red[tid >> 5] = ss;
    __syncthreads();
    float var = (red[0] + red[1] + red[2] + red[3]) / (float)EE;
    float inv = 1.0f / sqrtf(var + 1e-5f);
    const float4* gp = (const float4*)g;
    const float4* bp = (const float4*)b;
    float4 gg = gp[tid], bb = bp[tid];
    float4* op = (float4*)(out + (size_t)row * EE);
    op[tid] = make_float4(dx*inv*gg.x + bb.x, dy*inv*gg.y + bb.y,
                          dz*inv*gg.z + bb.z, dw*inv*gg.w + bb.w);
}

// ---------------- SIMT SGEMM (FFN; odd dims) --------------------------------
template <bool RELU, bool BIAS, bool RES>
__global__ void sgemm_kernel(const float* __restrict__ A, const float* __restrict__ W,
                             const float* __restrict__ bias, const float* __restrict__ res,
                             float* __restrict__ C, int M, int N, int K) {
    const int BM = 64, BN = 64, BK = 16;
    __shared__ float As[BK][BM + 1];
    __shared__ float Bs[BK][BN + 1];
    int tid = threadIdx.x;
    int tr = tid >> 4, tc = tid & 15;
    int row0 = blockIdx.y * BM, col0 = blockIdx.x * BN;
    float acc[4][4] = {};
    for (int k0 = 0; k0 < K; k0 += BK) {
        #pragma unroll
        for (int j = 0; j < (BM*BK)/256; j++) {
            int i = tid + j * 256;
            int m = i / BK, kk = i % BK;
            int gr = row0 + m, gk = k0 + kk;
            As[kk][m] = (gr < M && gk < K) ? A[(size_t)gr * K + gk] : 0.0f;
        }
        #pragma unroll
        for (int j = 0; j < (BK*BN)/256; j++) {
            int i = tid + j * 256;
            int kk = i / BN, n = i % BN;
            int gk = k0 + kk, gc = col0 + n;
            Bs[kk][n] = (gk < K && gc < N) ? W[(size_t)gk * N + gc] : 0.0f;
        }
        __syncthreads();
        #pragma unroll
        for (int kk = 0; kk < BK; kk++) {
            float a[4], bv[4];
            #pragma unroll
            for (int i = 0; i < 4; i++) a[i] = As[kk][tr*4 + i];
            #pragma unroll
            for (int j = 0; j < 4; j++) bv[j] = Bs[kk][tc*4 + j];
            #pragma unroll
            for (int i = 0; i < 4; i++)
                #pragma unroll
                for (int j = 0; j < 4; j++)
                    acc[i][j] = fmaf(a[i], bv[j], acc[i][j]);
        }
        __syncthreads();
    }
    #pragma unroll
    for (int i = 0; i < 4; i++) {
        int r = row0 + tr*4 + i;
        if (r >= M) continue;
        #pragma unroll
        for (int j = 0; j < 4; j++) {
            int c = col0 + tc*4 + j;
            if (c >= N) continue;
            float v = acc[i][j];
            if (BIAS) v += bias[c];
            if (RES)  v += res[(size_t)r * N + c];
            if (RELU) v = fmaxf(v, 0.0f);
            C[(size_t)r * N + c] = v;
        }
    }
}

// ---------------- QK^T: S[bh, t, s] = scale * q . k (causal block skip) ------
__global__ void qk_kernel(const float* __restrict__ qkv, float* __restrict__ S) {
    int sb = blockIdx.x, tb = blockIdx.y, bh = blockIdx.z;
    if (sb > tb) return;
    int b = bh >> 3, h = bh & 7;
    const float* qp = qkv + ((size_t)b*TT + tb*64) * QKVS + h*HD;
    const float* kp = qkv + 512 + ((size_t)b*TT + sb*64) * QKVS + h*HD;
    __shared__ float Qs[64][HD + 1];
    __shared__ float Ks[64][HD + 1];
    int tid = threadIdx.x;
    #pragma unroll
    for (int j = 0; j < 16; j++) {
        int i = tid + j * 256;
        int r = i >> 6, d = i & 63;
        Qs[r][d] = qp[(size_t)r * QKVS + d];
        Ks[r][d] = kp[(size_t)r * QKVS + d];
    }
    __syncthreads();
    int tr = tid >> 4, tc = tid & 15;
    float acc[4][4] = {};
    #pragma unroll
    for (int d = 0; d < HD; d++) {
        float a[4], bv[4];
        #pragma unroll
        for (int i = 0; i < 4; i++) a[i] = Qs[tr*4 + i][d];
        #pragma unroll
        for (int j = 0; j < 4; j++) bv[j] = Ks[tc*4 + j][d];
        #pragma unroll
        for (int i = 0; i < 4; i++)
            #pragma unroll
            for (int j = 0; j < 4; j++)
                acc[i][j] = fmaf(a[i], bv[j], acc[i][j]);
    }
    float* sp = S + ((size_t)bh * TT + tb*64) * TT + sb*64;
    #pragma unroll
    for (int i = 0; i < 4; i++)
        #pragma unroll
        for (int j = 0; j < 4; j++)
            sp[(size_t)(tr*4 + i) * TT + tc*4 + j] = acc[i][j] * 0.125f;
}

// ---------------- causal softmax row -> writes attn map into d_out ----------
__global__ void softmax_kernel(const float* __restrict__ S, float* __restrict__ out) {
    int row = blockIdx.x;
    int t = row & (TT - 1);
    const float* sp = S + (size_t)row * TT;
    float* op = out + (size_t)row * TT;
    int tid = threadIdx.x;
    float vals[4];
    float m = -1e30f;
    #pragma unroll
    for (int i = 0; i < 4; i++) {
        int s = tid + i * 256;
        vals[i] = (s <= t) ? sp[s] : -1e30f;
        m = fmaxf(m, vals[i]);
    }
    __shared__ float red[8];
    for (int o = 16; o; o >>= 1) m = fmaxf(m, __shfl_xor_sync(~0u, m, o));
    if ((tid & 31) == 0) red[tid >> 5] = m;
    __syncthreads();
    m = red[0];
    #pragma unroll
    for (int i = 1; i < 8; i++) m = fmaxf(m, red[i]);
    float e[4];
    float ssum = 0.0f;
    #pragma unroll
    for (int i = 0; i < 4; i++) {
        int s = tid + i * 256;
        e[i] = (s <= t) ? expf(vals[i] - m) : 0.0f;
        ssum += e[i];
    }
    __syncthreads();
    for (int o = 16; o; o >>= 1) ssum += __shfl_xor_sync(~0u, ssum, o);
    if ((tid & 31) == 0) red[tid >> 5] = ssum;
    __syncthreads();
    float tot = 0.0f;
    #pragma unroll
    for (int i = 0; i < 8; i++) tot += red[i];
    float inv = 1.0f / tot;
    #pragma unroll
    for (int i = 0; i < 4; i++) {
        int s = tid + i * 256;
        op[s] = e[i] * inv;
    }
}

// ---------------- Y = P @ V (P read back from d_out attn region) ------------
__global__ void av_kernel(const float* __restrict__ P, const float* __restrict__ qkv,
                          float* __restrict__ y) {
    int tb = blockIdx.x, bh = blockIdx.z;
    int b = bh >> 3, h = bh & 7;
    const float* pp = P + ((size_t)bh * TT + tb*64) * TT;
    const float* vbase = qkv + 1024;
    __shared__ float Ps[64][33];
    __shared__ float Vs[32][65];
    int tid = threadIdx.x;
    int tr = tid >> 4, tc = tid & 15;
    float acc[4][4] = {};
    int send = tb*64 + 64;
    for (int s0 = 0; s0 < send; s0 += 32) {
        #pragma unroll
        for (int j = 0; j < 8; j++) {
            int i = tid + j * 256;
            int m = i >> 5, kk = i & 31;
            Ps[m][kk] = pp[(size_t)m * TT + s0 + kk];
        }
        #pragma unroll
        for (int j = 0; j < 8; j++) {
            int i = tid + j * 256;
            int kk = i >> 6, d = i & 63;
            Vs[kk][d] = vbase[((size_t)b*TT + s0 + kk) * QKVS + h*HD + d];
        }
        __syncthreads();
        #pragma unroll
        for (int kk = 0; kk < 32; kk++) {
            float a[4], bv[4];
            #pragma unroll
            for (int i = 0; i < 4; i++) a[i] = Ps[tr*4 + i][kk];
            #pragma unroll
            for (int j = 0; j < 4; j++) bv[j] = Vs[kk][tc*4 + j];
            #pragma unroll
            for (int i = 0; i < 4; i++)
                #pragma unroll
                for (int j = 0; j < 4; j++)
                    acc[i][j] = fmaf(a[i], bv[j], acc[i][j]);
        }
        __syncthreads();
    }
    #pragma unroll
    for (int i = 0; i < 4; i++)
        #pragma unroll
        for (int j = 0; j < 4; j++)
            y[((size_t)b*TT + tb*64 + tr*4 + i) * EE + h*HD + tc*4 + j] = acc[i][j];
}

// ---------------- host orchestration ----------------------------------------
extern "C" void kernel_launch(void* const* d_in, const int* in_sizes, int n_in,
                              void* d_out, int out_size) {
    (void)in_sizes; (void)n_in; (void)out_size;
    const int*   idx     = (const int*)  d_in[0];
    const float* tok_emb = (const float*)d_in[1];
    const float* pos_emb = (const float*)d_in[2];
    const float* ln1_g   = (const float*)d_in[3];
    const float* ln1_b   = (const float*)d_in[4];
    const float* Wq      = (const float*)d_in[5];
    const float* Wk      = (const float*)d_in[6];
    const float* Wv      = (const float*)d_in[7];
    const float* Wo      = (const float*)d_in[8];
    const float* bo      = (const float*)d_in[9];
    const float* ln2_g   = (const float*)d_in[10];
    const float* ln2_b   = (const float*)d_in[11];
    const float* W1      = (const float*)d_in[12];
    const float* b1      = (const float*)d_in[13];
    const float* W2      = (const float*)d_in[14];
    const float* b2      = (const float*)d_in[15];
    const float* lnf_g   = (const float*)d_in[16];
    const float* lnf_b   = (const float*)d_in[17];
    const float* Wlm     = (const float*)d_in[18];

    float* out    = (float*)d_out;
    float* logits = out;
    float* attn   = out + LOGITS_N;

    float *gx, *gh, *gqkv, *gy, *gu, *gS, *gWlmT, *gWT;
    cudaGetSymbolAddress((void**)&gx, d_x);
    cudaGetSymbolAddress((void**)&gh, d_h);
    cudaGetSymbolAddress((void**)&gqkv, d_qkv);
    cudaGetSymbolAddress((void**)&gy, d_y);
    cudaGetSymbolAddress((void**)&gu, d_u);
    cudaGetSymbolAddress((void**)&gS, d_S);
    cudaGetSymbolAddress((void**)&gWlmT, d_WlmT);
    cudaGetSymbolAddress((void**)&gWT, d_WT);

    cudaFuncSetAttribute(mma_gemm<false,false,false,false>,
                         cudaFuncAttributeMaxDynamicSharedMemorySize, GEMM_SMEM);
    cudaFuncSetAttribute(mma_gemm<true,true,false,false>,
                         cudaFuncAttributeMaxDynamicSharedMemorySize, GEMM_SMEM);
    cudaFuncSetAttribute(mma_gemm<false,false,false,true>,
                         cudaFuncAttributeMaxDynamicSharedMemorySize, GEMM_SMEM);

    // Transpose weights: per layer pack [WqT; WkT; WvT] (1536x512) + WoT (512x512)
    {
        dim3 tb(32, 8);
        for (int l = 0; l < LL; l++) {
            float* base = gWT + (size_t)l * 4 * EE * EE;
            transpose_kernel<<<dim3(EE/32, EE/32), tb>>>(Wq + (size_t)l*EE*EE, base,                 EE, EE);
            transpose_kernel<<<dim3(EE/32, EE/32), tb>>>(Wk + (size_t)l*EE*EE, base + (size_t)512*EE, EE, EE);
            transpose_kernel<<<dim3(EE/32, EE/32), tb>>>(Wv + (size_t)l*EE*EE, base + (size_t)1024*EE, EE, EE);
            transpose_kernel<<<dim3(EE/32, EE/32), tb>>>(Wo + (size_t)l*EE*EE, base + (size_t)1536*EE, EE, EE);
        }
        transpose_kernel<<<dim3(VV/32, EE/32), tb>>>(Wlm, gWlmT, EE, VV);
    }

    embed_kernel<<<BT, 128>>>(idx, tok_emb, pos_emb, gx);

    for (int l = 0; l < LL; l++) {
        float* base = gWT + (size_t)l * 4 * EE * EE;
        const float* qkvT = base;
        const float* woT  = base + (size_t)1536*EE;
        const float* w1 = W1 + (size_t)l*EE*HIDN;
        const float* w2 = W2 + (size_t)l*HIDN*EE;
        float* attn_l = attn + (size_t)l * ATT_PER_L;

        ln_kernel<<<BT, 128>>>(gx, gh, ln1_g + l*EE, ln1_b + l*EE);

        // fused QKV: [4096,1536] = h @ [512,1536]
        mma_gemm<false,false,false,false><<<dim3(QKVS/128, BT/128), 256, GEMM_SMEM>>>(
            gh, qkvT, nullptr, nullptr, gqkv, BT, QKVS, EE);

        qk_kernel<<<dim3(TT/64, TT/64, BB*HH), 256>>>(gqkv, gS);
        softmax_kernel<<<BHT, 256>>>(gS, attn_l);
        av_kernel<<<dim3(TT/64, 1, BB*HH), 256>>>(attn_l, gqkv, gy);

        // x = x + y @ Wo + bo
        mma_gemm<true,true,false,false><<<dim3(EE/128, BT/128), 256, GEMM_SMEM>>>(
            gy, woT, bo + l*EE, gx, gx, BT, EE, EE);

        ln_kernel<<<BT, 128>>>(gx, gh, ln2_g + l*EE, ln2_b + l*EE);

        {   // u = relu(h @ W1 + b1)  (N=100, SIMT)
            dim3 grid((HIDN + 63)/64, BT/64);
            sgemm_kernel<true,true,false><<<grid, 256>>>(gh, w1, b1 + l*HIDN, nullptr, gu, BT, HIDN, EE);
        }
        {   // x = x + u @ W2 + b2    (K=100, SIMT)
            dim3 grid(EE/64, BT/64);
            sgemm_kernel<false,true,true><<<grid, 256>>>(gu, w2, b2 + l*EE, gx, gx, BT, EE, HIDN);
        }
    }

    ln_kernel<<<BT, 128>>>(gx, gh, lnf_g, lnf_b);
    // logits: 3-term bf16 + M-fastest grid for L2-friendly weight streaming
    mma_gemm<false,false,false,true><<<dim3(BT/128, VV/128), 256, GEMM_SMEM>>>(
        gh, gWlmT, nullptr, nullptr, logits, BT, VV, EE);
}

// round 8
// speedup vs baseline: 2.9513x; 1.1792x over previous
#include <cuda_runtime.h>
#include <cuda_bf16.h>
#include <cstdint>
#include <cstddef>

// Problem dims
#define BB 4
#define TT 1024
#define EE 512
#define HH 8
#define LL 4
#define VV 32000
#define HIDN 100
#define HIDP 128
#define HD 64
#define BT (BB*TT)          // 4096
#define BHT (BB*HH*TT)      // 32768
#define QKVS 1536           // packed qkv row stride
#define ATT_PER_L ((size_t)BB*HH*TT*TT)   // 33,554,432
#define LOGITS_N ((size_t)BT*VV)          // 131,072,000

// ---------------- scratch (device globals; no allocations allowed) ----------
__device__ float d_x[BT*EE];
__device__ float d_h[BT*EE];
__device__ float d_qkv[(size_t)BT*QKVS];
__device__ float d_y[BT*EE];
__device__ float d_u[BT*HIDP];
__device__ float d_S[(size_t)BB*HH*TT*TT];     // raw scores, 128 MB
__device__ float d_vT[(size_t)BB*EE*TT];       // V transposed per batch [b][e][s]
__device__ float d_WlmT[(size_t)VV*EE];        // Wlm^T  [V,E]
__device__ float d_WT[(size_t)LL*4*EE*EE];     // per-layer [qkvT(1536,512); woT(512,512)]
__device__ float d_W1Tp[(size_t)LL*HIDP*EE];   // padded W1^T [128,512]
__device__ float d_W2Tp[(size_t)LL*EE*HIDP];   // padded W2^T [512,128]
__device__ float d_b1p[LL*HIDP];

// ======================= bf16 mma helpers ====================================
#define TILE_F (128*36)           // floats per smem tile (padded rows)
#define GEMM_SMEM (4*TILE_F*4)    // bytes: 2 stages x (A+B)
#define AV_SMEM  (2*(128*36 + 64*36)*4)

__device__ __forceinline__ uint32_t smem_u32(const void* p) {
    uint32_t a;
    asm("{ .reg .u64 t; cvta.to.shared.u64 t, %1; cvt.u32.u64 %0, t; }"
        : "=r"(a) : "l"(p));
    return a;
}
__device__ __forceinline__ void cp16(uint32_t saddr, const void* g) {
    asm volatile("cp.async.cg.shared.global [%0], [%1], 16;" :: "r"(saddr), "l"(g));
}
__device__ __forceinline__ uint32_t pack2_hi(float f0, float f1) {
    uint32_t r;
    asm("cvt.rn.bf16x2.f32 %0, %1, %2;" : "=r"(r) : "f"(f1), "f"(f0));
    return r;
}
__device__ __forceinline__ uint32_t pack2_lo(float f0, float f1, uint32_t hi) {
    float h0 = __uint_as_float(hi << 16);
    float h1 = __uint_as_float(hi & 0xffff0000u);
    uint32_t r;
    asm("cvt.rn.bf16x2.f32 %0, %1, %2;" : "=r"(r) : "f"(f1 - h1), "f"(f0 - h0));
    return r;
}
__device__ __forceinline__ void mma_bf16(float c[4], const uint32_t a[4], const uint32_t b[2]) {
    asm volatile(
        "mma.sync.aligned.m16n8k16.row.col.f32.bf16.bf16.f32 "
        "{%0,%1,%2,%3}, {%4,%5,%6,%7}, {%8,%9}, {%0,%1,%2,%3};"
        : "+f"(c[0]), "+f"(c[1]), "+f"(c[2]), "+f"(c[3])
        : "r"(a[0]), "r"(a[1]), "r"(a[2]), "r"(a[3]), "r"(b[0]), "r"(b[1]));
}

// ======================= bf16 mma.sync GEMM (3-term compensated) =============
// C[M,N] = A[M,K] @ W[K,N], W given TRANSPOSED as BT_[N,K] row-major.
template <bool BIAS, bool RES, bool RELU, bool SWAPG>
__global__ void __launch_bounds__(256, 2)
mma_gemm(const float* __restrict__ A, const float* __restrict__ BT_,
         const float* __restrict__ bias, const float* __restrict__ res,
         float* __restrict__ C, int M, int N, int K) {
    extern __shared__ float smem_f[];
    float* As = smem_f;
    float* Bs = smem_f + 2*TILE_F;

    const int tid = threadIdx.x;
    const int wid = tid >> 5;
    const int lane = tid & 31;
    const int g = lane >> 2, q = lane & 3;
    const int wm = wid & 1, wn = wid >> 1;

    const int row0 = (SWAPG ? blockIdx.x : blockIdx.y) * 128;
    const int col0 = (SWAPG ? blockIdx.y : blockIdx.x) * 128;
    const float* Ap = A + (size_t)row0 * K;
    const float* Bp = BT_ + (size_t)col0 * K;

    const uint32_t sA0 = smem_u32(As);
    const uint32_t sB0 = smem_u32(Bs);

    const int NK = K >> 5;

    int lrow[4], lc4[4];
    #pragma unroll
    for (int j = 0; j < 4; j++) {
        int i = tid + j * 256;
        lrow[j] = i >> 3;
        lc4[j] = i & 7;
    }

    auto load_stage = [&](int buf, int kt) {
        const int k0 = kt << 5;
        const uint32_t offA = sA0 + buf * TILE_F * 4;
        const uint32_t offB = sB0 + buf * TILE_F * 4;
        #pragma unroll
        for (int j = 0; j < 4; j++) {
            uint32_t so = (uint32_t)(lrow[j] * 36 + lc4[j] * 4) * 4;
            cp16(offA + so, Ap + (size_t)lrow[j] * K + k0 + lc4[j] * 4);
            cp16(offB + so, Bp + (size_t)lrow[j] * K + k0 + lc4[j] * 4);
        }
        asm volatile("cp.async.commit_group;");
    };

    float acc[4][4][4];
    #pragma unroll
    for (int i = 0; i < 4; i++)
        #pragma unroll
        for (int j = 0; j < 4; j++)
            #pragma unroll
            for (int t = 0; t < 4; t++) acc[i][j][t] = 0.0f;

    load_stage(0, 0);

    int buf = 0;
    for (int kt = 0; kt < NK; kt++) {
        if (kt + 1 < NK) {
            load_stage(buf ^ 1, kt + 1);
            asm volatile("cp.async.wait_group 1;");
        } else {
            asm volatile("cp.async.wait_group 0;");
        }
        __syncthreads();

        const float* as = As + buf * TILE_F + (wm * 64 + g) * 36 + 2 * q;
        const float* bs = Bs + buf * TILE_F + (wn * 32 + g) * 36 + 2 * q;
        #pragma unroll
        for (int s = 0; s < 2; s++) {
            const int k0 = s * 16;
            uint32_t ah[4][4], al[4][4], bh[4][2], bl[4][2];
            #pragma unroll
            for (int i = 0; i < 4; i++) {
                const float* p = as + i * 16 * 36 + k0;
                float2 x0 = *(const float2*)(p);
                float2 x1 = *(const float2*)(p + 8 * 36);
                float2 x2 = *(const float2*)(p + 8);
                float2 x3 = *(const float2*)(p + 8 * 36 + 8);
                ah[i][0] = pack2_hi(x0.x, x0.y); al[i][0] = pack2_lo(x0.x, x0.y, ah[i][0]);
                ah[i][1] = pack2_hi(x1.x, x1.y); al[i][1] = pack2_lo(x1.x, x1.y, ah[i][1]);
                ah[i][2] = pack2_hi(x2.x, x2.y); al[i][2] = pack2_lo(x2.x, x2.y, ah[i][2]);
                ah[i][3] = pack2_hi(x3.x, x3.y); al[i][3] = pack2_lo(x3.x, x3.y, ah[i][3]);
            }
            #pragma unroll
            for (int j = 0; j < 4; j++) {
                const float* p = bs + j * 8 * 36 + k0;
                float2 y0 = *(const float2*)(p);
                float2 y1 = *(const float2*)(p + 8);
                bh[j][0] = pack2_hi(y0.x, y0.y); bl[j][0] = pack2_lo(y0.x, y0.y, bh[j][0]);
                bh[j][1] = pack2_hi(y1.x, y1.y); bl[j][1] = pack2_lo(y1.x, y1.y, bh[j][1]);
            }
            #pragma unroll
            for (int i = 0; i < 4; i++)
                #pragma unroll
                for (int j = 0; j < 4; j++) {
                    mma_bf16(acc[i][j], ah[i], bl[j]);
                    mma_bf16(acc[i][j], al[i], bh[j]);
                    mma_bf16(acc[i][j], ah[i], bh[j]);
                }
        }
        __syncthreads();
        buf ^= 1;
    }

    const int m0 = row0 + wm * 64 + g;
    const int n0 = col0 + wn * 32 + 2 * q;
    #pragma unroll
    for (int i = 0; i < 4; i++) {
        #pragma unroll
        for (int j = 0; j < 4; j++) {
            int c = n0 + j * 8;
            float b0 = 0.f, b1 = 0.f;
            if (BIAS) { b0 = bias[c]; b1 = bias[c + 1]; }
            #pragma unroll
            for (int hh = 0; hh < 2; hh++) {
                int r = m0 + i * 16 + hh * 8;
                float v0 = acc[i][j][hh * 2 + 0] + b0;
                float v1 = acc[i][j][hh * 2 + 1] + b1;
                if (RES) {
                    const float* rp = res + (size_t)r * N + c;
                    v0 += rp[0]; v1 += rp[1];
                }
                if (RELU) { v0 = fmaxf(v0, 0.f); v1 = fmaxf(v1, 0.f); }
                float2* cp = (float2*)(C + (size_t)r * N + c);
                *cp = make_float2(v0, v1);
            }
        }
    }
}

// ======================= QK^T via bf16 mma ===================================
// S[bh, t, s] = 0.125 * q[t,:] . k[s,:].  grid (sb 8, tb 8, bh 32), skip sb>tb.
__global__ void __launch_bounds__(256, 2)
qk_mma(const float* __restrict__ qkv, float* __restrict__ S) {
    if (blockIdx.x > blockIdx.y) return;
    extern __shared__ float smem_f[];
    float* As = smem_f;
    float* Bs = smem_f + 2*TILE_F;

    const int tid = threadIdx.x;
    const int wid = tid >> 5;
    const int lane = tid & 31;
    const int g = lane >> 2, q = lane & 3;
    const int wm = wid & 1, wn = wid >> 1;

    const int row0 = blockIdx.y * 128;     // t
    const int col0 = blockIdx.x * 128;     // s
    const int b = blockIdx.z >> 3, h = blockIdx.z & 7;
    const float* Ap = qkv + ((size_t)b*TT + row0) * QKVS + h*HD;          // Q
    const float* Bp = qkv + 512 + ((size_t)b*TT + col0) * QKVS + h*HD;    // K

    const uint32_t sA0 = smem_u32(As);
    const uint32_t sB0 = smem_u32(Bs);

    int lrow[4], lc4[4];
    #pragma unroll
    for (int j = 0; j < 4; j++) {
        int i = tid + j * 256;
        lrow[j] = i >> 3;
        lc4[j] = i & 7;
    }

    auto load_stage = [&](int buf, int kt) {
        const int k0 = kt << 5;
        const uint32_t offA = sA0 + buf * TILE_F * 4;
        const uint32_t offB = sB0 + buf * TILE_F * 4;
        #pragma unroll
        for (int j = 0; j < 4; j++) {
            uint32_t so = (uint32_t)(lrow[j] * 36 + lc4[j] * 4) * 4;
            cp16(offA + so, Ap + (size_t)lrow[j] * QKVS + k0 + lc4[j] * 4);
            cp16(offB + so, Bp + (size_t)lrow[j] * QKVS + k0 + lc4[j] * 4);
        }
        asm volatile("cp.async.commit_group;");
    };

    float acc[4][4][4];
    #pragma unroll
    for (int i = 0; i < 4; i++)
        #pragma unroll
        for (int j = 0; j < 4; j++)
            #pragma unroll
            for (int t = 0; t < 4; t++) acc[i][j][t] = 0.0f;

    load_stage(0, 0);

    int buf = 0;
    for (int kt = 0; kt < 2; kt++) {       // K = 64
        if (kt == 0) {
            load_stage(1, 1);
            asm volatile("cp.async.wait_group 1;");
        } else {
            asm volatile("cp.async.wait_group 0;");
        }
        __syncthreads();

        const float* as = As + buf * TILE_F + (wm * 64 + g) * 36 + 2 * q;
        const float* bs = Bs + buf * TILE_F + (wn * 32 + g) * 36 + 2 * q;
        #pragma unroll
        for (int s = 0; s < 2; s++) {
            const int k0 = s * 16;
            uint32_t ah[4][4], al[4][4], bh[4][2], bl[4][2];
            #pragma unroll
            for (int i = 0; i < 4; i++) {
                const float* p = as + i * 16 * 36 + k0;
                float2 x0 = *(const float2*)(p);
                float2 x1 = *(const float2*)(p + 8 * 36);
                float2 x2 = *(const float2*)(p + 8);
                float2 x3 = *(const float2*)(p + 8 * 36 + 8);
                ah[i][0] = pack2_hi(x0.x, x0.y); al[i][0] = pack2_lo(x0.x, x0.y, ah[i][0]);
                ah[i][1] = pack2_hi(x1.x, x1.y); al[i][1] = pack2_lo(x1.x, x1.y, ah[i][1]);
                ah[i][2] = pack2_hi(x2.x, x2.y); al[i][2] = pack2_lo(x2.x, x2.y, ah[i][2]);
                ah[i][3] = pack2_hi(x3.x, x3.y); al[i][3] = pack2_lo(x3.x, x3.y, ah[i][3]);
            }
            #pragma unroll
            for (int j = 0; j < 4; j++) {
                const float* p = bs + j * 8 * 36 + k0;
                float2 y0 = *(const float2*)(p);
                float2 y1 = *(const float2*)(p + 8);
                bh[j][0] = pack2_hi(y0.x, y0.y); bl[j][0] = pack2_lo(y0.x, y0.y, bh[j][0]);
                bh[j][1] = pack2_hi(y1.x, y1.y); bl[j][1] = pack2_lo(y1.x, y1.y, bh[j][1]);
            }
            #pragma unroll
            for (int i = 0; i < 4; i++)
                #pragma unroll
                for (int j = 0; j < 4; j++) {
                    mma_bf16(acc[i][j], ah[i], bl[j]);
                    mma_bf16(acc[i][j], al[i], bh[j]);
                    mma_bf16(acc[i][j], ah[i], bh[j]);
                }
        }
        __syncthreads();
        buf ^= 1;
    }

    float* Sp = S + (size_t)blockIdx.z * TT * TT;
    const int m0 = row0 + wm * 64 + g;
    const int n0 = col0 + wn * 32 + 2 * q;
    #pragma unroll
    for (int i = 0; i < 4; i++)
        #pragma unroll
        for (int j = 0; j < 4; j++) {
            int c = n0 + j * 8;
            #pragma unroll
            for (int hh = 0; hh < 2; hh++) {
                int r = m0 + i * 16 + hh * 8;
                float2* cp = (float2*)(Sp + (size_t)r * TT + c);
                *cp = make_float2(acc[i][j][hh*2+0] * 0.125f, acc[i][j][hh*2+1] * 0.125f);
            }
        }
}

// ======================= P @ V via bf16 mma ==================================
// Y[b, t, h*64+d] = sum_s P[bh,t,s] * vT[b, h*64+d, s].  Tile 128(t) x 64(d).
// grid (tb 8, 1, bh 32).  Causal: K runs to row0+128.
#define AV_AF (128*36)
#define AV_BF (64*36)
__global__ void __launch_bounds__(256, 2)
av_mma(const float* __restrict__ P, const float* __restrict__ vT,
       float* __restrict__ y) {
    extern __shared__ float smem_f[];
    float* As = smem_f;                       // [2][AV_AF]
    float* Bs = smem_f + 2*AV_AF;             // [2][AV_BF]

    const int tid = threadIdx.x;
    const int wid = tid >> 5;
    const int lane = tid & 31;
    const int g = lane >> 2, q = lane & 3;
    const int wm = wid & 3, wn = wid >> 2;    // 4 x 2 warp grid (32x32 tiles)

    const int row0 = blockIdx.x * 128;        // t
    const int b = blockIdx.z >> 3, h = blockIdx.z & 7;
    const float* Ap = P + (size_t)blockIdx.z * TT * TT + (size_t)row0 * TT;
    const float* Bp = vT + ((size_t)b*EE + h*HD) * TT;

    const uint32_t sA0 = smem_u32(As);
    const uint32_t sB0 = smem_u32(Bs);

    const int NK = (row0 >> 5) + 4;           // (row0+128)/32 chunks

    // A loads: 1024 float4 (4/thread); B loads: 512 float4 (2/thread)
    int arow[4], ac4[4], brow[2], bc4[2];
    #pragma unroll
    for (int j = 0; j < 4; j++) {
        int i = tid + j * 256;
        arow[j] = i >> 3; ac4[j] = i & 7;
    }
    #pragma unroll
    for (int j = 0; j < 2; j++) {
        int i = tid + j * 256;
        brow[j] = i >> 3; bc4[j] = i & 7;
    }

    auto load_stage = [&](int buf, int kt) {
        const int k0 = kt << 5;
        const uint32_t offA = sA0 + buf * AV_AF * 4;
        const uint32_t offB = sB0 + buf * AV_BF * 4;
        #pragma unroll
        for (int j = 0; j < 4; j++) {
            uint32_t so = (uint32_t)(arow[j] * 36 + ac4[j] * 4) * 4;
            cp16(offA + so, Ap + (size_t)arow[j] * TT + k0 + ac4[j] * 4);
        }
        #pragma unroll
        for (int j = 0; j < 2; j++) {
            uint32_t so = (uint32_t)(brow[j] * 36 + bc4[j] * 4) * 4;
            cp16(offB + so, Bp + (size_t)brow[j] * TT + k0 + bc4[j] * 4);
        }
        asm volatile("cp.async.commit_group;");
    };

    float acc[2][4][4];
    #pragma unroll
    for (int i = 0; i < 2; i++)
        #pragma unroll
        for (int j = 0; j < 4; j++)
            #pragma unroll
            for (int t = 0; t < 4; t++) acc[i][j][t] = 0.0f;

    load_stage(0, 0);

    int buf = 0;
    for (int kt = 0; kt < NK; kt++) {
        if (kt + 1 < NK) {
            load_stage(buf ^ 1, kt + 1);
            asm volatile("cp.async.wait_group 1;");
        } else {
            asm volatile("cp.async.wait_group 0;");
        }
        __syncthreads();

        const float* as = As + buf * AV_AF + (wm * 32 + g) * 36 + 2 * q;
        const float* bs = Bs + buf * AV_BF + (wn * 32 + g) * 36 + 2 * q;
        #pragma unroll
        for (int s = 0; s < 2; s++) {
            const int k0 = s * 16;
            uint32_t ah[2][4], al[2][4], bh[4][2], bl[4][2];
            #pragma unroll
            for (int i = 0; i < 2; i++) {
                const float* p = as + i * 16 * 36 + k0;
                float2 x0 = *(const float2*)(p);
                float2 x1 = *(const float2*)(p + 8 * 36);
                float2 x2 = *(const float2*)(p + 8);
                float2 x3 = *(const float2*)(p + 8 * 36 + 8);
                ah[i][0] = pack2_hi(x0.x, x0.y); al[i][0] = pack2_lo(x0.x, x0.y, ah[i][0]);
                ah[i][1] = pack2_hi(x1.x, x1.y); al[i][1] = pack2_lo(x1.x, x1.y, ah[i][1]);
                ah[i][2] = pack2_hi(x2.x, x2.y); al[i][2] = pack2_lo(x2.x, x2.y, ah[i][2]);
                ah[i][3] = pack2_hi(x3.x, x3.y); al[i][3] = pack2_lo(x3.x, x3.y, ah[i][3]);
            }
            #pragma unroll
            for (int j = 0; j < 4; j++) {
                const float* p = bs + j * 8 * 36 + k0;
                float2 y0 = *(const float2*)(p);
                float2 y1 = *(const float2*)(p + 8);
                bh[j][0] = pack2_hi(y0.x, y0.y); bl[j][0] = pack2_lo(y0.x, y0.y, bh[j][0]);
                bh[j][1] = pack2_hi(y1.x, y1.y); bl[j][1] = pack2_lo(y1.x, y1.y, bh[j][1]);
            }
            #pragma unroll
            for (int i = 0; i < 2; i++)
                #pragma unroll
                for (int j = 0; j < 4; j++) {
                    mma_bf16(acc[i][j], ah[i], bl[j]);
                    mma_bf16(acc[i][j], al[i], bh[j]);
                    mma_bf16(acc[i][j], ah[i], bh[j]);
                }
        }
        __syncthreads();
        buf ^= 1;
    }

    const int m0 = row0 + wm * 32 + g;
    const int n0 = wn * 32 + 2 * q;
    #pragma unroll
    for (int i = 0; i < 2; i++)
        #pragma unroll
        for (int j = 0; j < 4; j++) {
            int c = n0 + j * 8;
            #pragma unroll
            for (int hh = 0; hh < 2; hh++) {
                int r = m0 + i * 16 + hh * 8;
                float2* cp = (float2*)(y + ((size_t)b*TT + r) * EE + h*HD + c);
                *cp = make_float2(acc[i][j][hh*2+0], acc[i][j][hh*2+1]);
            }
        }
}

// ---------------- transpose W[K,N] -> WT[N,K] --------------------------------
__global__ void transpose_kernel(const float* __restrict__ W, float* __restrict__ WT,
                                 int K, int N) {
    __shared__ float t[32][33];
    int n0 = blockIdx.x * 32, k0 = blockIdx.y * 32;
    int x = threadIdx.x, y = threadIdx.y;   // 32 x 8
    #pragma unroll
    for (int j = 0; j < 32; j += 8)
        t[y + j][x] = W[(size_t)(k0 + y + j) * N + n0 + x];
    __syncthreads();
    #pragma unroll
    for (int j = 0; j < 32; j += 8)
        WT[(size_t)(n0 + y + j) * K + k0 + x] = t[x][y + j];
}

// ---------------- padded transpose: WT[Np,Kp] from W[K,N] (zero fill) --------
__global__ void pad_transpose_kernel(const float* __restrict__ W, float* __restrict__ WT,
                                     int K, int N, int Kp, int Np) {
    __shared__ float t[32][33];
    int n0 = blockIdx.x * 32, k0 = blockIdx.y * 32;
    int x = threadIdx.x, y = threadIdx.y;
    #pragma unroll
    for (int j = 0; j < 32; j += 8) {
        int kk = k0 + y + j, nn = n0 + x;
        t[y + j][x] = (kk < K && nn < N) ? W[(size_t)kk * N + nn] : 0.0f;
    }
    __syncthreads();
    #pragma unroll
    for (int j = 0; j < 32; j += 8)
        WT[(size_t)(n0 + y + j) * Kp + k0 + x] = t[x][y + j];
}

// ---------------- pad b1 -----------------------------------------------------
__global__ void pad_b1_kernel(const float* __restrict__ b1, float* __restrict__ b1p) {
    int l = blockIdx.x, tid = threadIdx.x;
    b1p[l * HIDP + tid] = (tid < HIDN) ? b1[l * HIDN + tid] : 0.0f;
}

// ---------------- transpose V -> vT[b][e][s] --------------------------------
__global__ void vtrans_kernel(const float* __restrict__ qkv, float* __restrict__ vT) {
    __shared__ float t[32][33];
    int s0 = blockIdx.x * 32, e0 = blockIdx.y * 32, b = blockIdx.z;
    int x = threadIdx.x, y = threadIdx.y;   // 32 x 8
    #pragma unroll
    for (int j = 0; j < 32; j += 8)
        t[y + j][x] = qkv[((size_t)b*TT + s0 + y + j) * QKVS + 1024 + e0 + x];
    __syncthreads();
    #pragma unroll
    for (int j = 0; j < 32; j += 8)
        vT[((size_t)b*EE + e0 + y + j) * TT + s0 + x] = t[x][y + j];
}

// ---------------- embed: x = tok_emb[idx] + pos_emb -------------------------
__global__ void embed_kernel(const int* __restrict__ idx,
                             const float* __restrict__ tok,
                             const float* __restrict__ pos,
                             float* __restrict__ x) {
    int row = blockIdx.x;
    int t = row & (TT - 1);
    int token = idx[row];
    const float4* tp = (const float4*)(tok + (size_t)token * EE);
    const float4* pp = (const float4*)(pos + (size_t)t * EE);
    float4* xp = (float4*)(x + (size_t)row * EE);
    int c = threadIdx.x;
    float4 a = tp[c], b = pp[c];
    xp[c] = make_float4(a.x + b.x, a.y + b.y, a.z + b.z, a.w + b.w);
}

// ---------------- layernorm --------------------------------------------------
__global__ void ln_kernel(const float* __restrict__ x, float* __restrict__ out,
                          const float* __restrict__ g, const float* __restrict__ b) {
    int row = blockIdx.x;
    int tid = threadIdx.x;
    const float4* xp = (const float4*)(x + (size_t)row * EE);
    float4 v = xp[tid];
    float s = v.x + v.y + v.z + v.w;
    __shared__ float red[4];
    for (int o = 16; o; o >>= 1) s += __shfl_xor_sync(~0u, s, o);
    if ((tid & 31) == 0) red[tid >> 5] = s;
    __syncthreads();
    float mean = (red[0] + red[1] + red[2] + red[3]) / (float)EE;
    float dx = v.x - mean, dy = v.y - mean, dz = v.z - mean, dw = v.w - mean;
    float ss = dx*dx + dy*dy + dz*dz + dw*dw;
    __syncthreads();
    for (int o = 16; o; o >>= 1) ss += __shfl_xor_sync(~0u, ss, o);
    if ((tid & 31) == 0) red[tid >> 5] = ss;
    __syncthreads();
    float var = (red[0] + red[1] + red[2] + red[3]) / (float)EE;
    float inv = 1.0f / sqrtf(var + 1e-5f);
    const float4* gp = (const float4*)g;
    const float4* bp = (const float4*)b;
    float4 gg = gp[tid], bb = bp[tid];
    float4* op = (float4*)(out + (size_t)row * EE);
    op[tid] = make_float4(dx*inv*gg.x + bb.x, dy*inv*gg.y + bb.y,
                          dz*inv*gg.z + bb.z, dw*inv*gg.w + bb.w);
}

// ---------------- causal softmax row -> writes attn map into d_out ----------
__global__ void softmax_kernel(const float* __restrict__ S, float* __restrict__ out) {
    int row = blockIdx.x;
    int t = row & (TT - 1);
    const float* sp = S + (size_t)row * TT;
    float* op = out + (size_t)row * TT;
    int tid = threadIdx.x;
    float vals[4];
    float m = -1e30f;
    #pragma unroll
    for (int i = 0; i < 4; i++) {
        int s = tid + i * 256;
        vals[i] = (s <= t) ? sp[s] : -1e30f;
        m = fmaxf(m, vals[i]);
    }
    __shared__ float red[8];
    for (int o = 16; o; o >>= 1) m = fmaxf(m, __shfl_xor_sync(~0u, m, o));
    if ((tid & 31) == 0) red[tid >> 5] = m;
    __syncthreads();
    m = red[0];
    #pragma unroll
    for (int i = 1; i < 8; i++) m = fmaxf(m, red[i]);
    float e[4];
    float ssum = 0.0f;
    #pragma unroll
    for (int i = 0; i < 4; i++) {
        int s = tid + i * 256;
        e[i] = (s <= t) ? expf(vals[i] - m) : 0.0f;
        ssum += e[i];
    }
    __syncthreads();
    for (int o = 16; o; o >>= 1) ssum += __shfl_xor_sync(~0u, ssum, o);
    if ((tid & 31) == 0) red[tid >> 5] = ssum;
    __syncthreads();
    float tot = 0.0f;
    #pragma unroll
    for (int i = 0; i < 8; i++) tot += red[i];
    float inv = 1.0f / tot;
    #pragma unroll
    for (int i = 0; i < 4; i++) {
        int s = tid + i * 256;
        op[s] = e[i] * inv;
    }
}

// ---------------- host orchestration ----------------------------------------
extern "C" void kernel_launch(void* const* d_in, const int* in_sizes, int n_in,
                              void* d_out, int out_size) {
    (void)in_sizes; (void)n_in; (void)out_size;
    const int*   idx     = (const int*)  d_in[0];
    const float* tok_emb = (const float*)d_in[1];
    const float* pos_emb = (const float*)d_in[2];
    const float* ln1_g   = (const float*)d_in[3];
    const float* ln1_b   = (const float*)d_in[4];
    const float* Wq      = (const float*)d_in[5];
    const float* Wk      = (const float*)d_in[6];
    const float* Wv      = (const float*)d_in[7];
    const float* Wo      = (const float*)d_in[8];
    const float* bo      = (const float*)d_in[9];
    const float* ln2_g   = (const float*)d_in[10];
    const float* ln2_b   = (const float*)d_in[11];
    const float* W1      = (const float*)d_in[12];
    const float* b1      = (const float*)d_in[13];
    const float* W2      = (const float*)d_in[14];
    const float* b2      = (const float*)d_in[15];
    const float* lnf_g   = (const float*)d_in[16];
    const float* lnf_b   = (const float*)d_in[17];
    const float* Wlm     = (const float*)d_in[18];

    float* out    = (float*)d_out;
    float* logits = out;
    float* attn   = out + LOGITS_N;

    float *gx, *gh, *gqkv, *gy, *gu, *gS, *gvT, *gWlmT, *gWT, *gW1Tp, *gW2Tp, *gb1p;
    cudaGetSymbolAddress((void**)&gx, d_x);
    cudaGetSymbolAddress((void**)&gh, d_h);
    cudaGetSymbolAddress((void**)&gqkv, d_qkv);
    cudaGetSymbolAddress((void**)&gy, d_y);
    cudaGetSymbolAddress((void**)&gu, d_u);
    cudaGetSymbolAddress((void**)&gS, d_S);
    cudaGetSymbolAddress((void**)&gvT, d_vT);
    cudaGetSymbolAddress((void**)&gWlmT, d_WlmT);
    cudaGetSymbolAddress((void**)&gWT, d_WT);
    cudaGetSymbolAddress((void**)&gW1Tp, d_W1Tp);
    cudaGetSymbolAddress((void**)&gW2Tp, d_W2Tp);
    cudaGetSymbolAddress((void**)&gb1p, d_b1p);

    cudaFuncSetAttribute(mma_gemm<false,false,false,false>,
                         cudaFuncAttributeMaxDynamicSharedMemorySize, GEMM_SMEM);
    cudaFuncSetAttribute(mma_gemm<true,true,false,false>,
                         cudaFuncAttributeMaxDynamicSharedMemorySize, GEMM_SMEM);
    cudaFuncSetAttribute(mma_gemm<true,false,true,false>,
                         cudaFuncAttributeMaxDynamicSharedMemorySize, GEMM_SMEM);
    cudaFuncSetAttribute(mma_gemm<false,false,false,true>,
                         cudaFuncAttributeMaxDynamicSharedMemorySize, GEMM_SMEM);
    cudaFuncSetAttribute(qk_mma, cudaFuncAttributeMaxDynamicSharedMemorySize, GEMM_SMEM);
    cudaFuncSetAttribute(av_mma, cudaFuncAttributeMaxDynamicSharedMemorySize, AV_SMEM);

    // Weight prep
    {
        dim3 tb(32, 8);
        for (int l = 0; l < LL; l++) {
            float* base = gWT + (size_t)l * 4 * EE * EE;
            transpose_kernel<<<dim3(EE/32, EE/32), tb>>>(Wq + (size_t)l*EE*EE, base,                 EE, EE);
            transpose_kernel<<<dim3(EE/32, EE/32), tb>>>(Wk + (size_t)l*EE*EE, base + (size_t)512*EE, EE, EE);
            transpose_kernel<<<dim3(EE/32, EE/32), tb>>>(Wv + (size_t)l*EE*EE, base + (size_t)1024*EE, EE, EE);
            transpose_kernel<<<dim3(EE/32, EE/32), tb>>>(Wo + (size_t)l*EE*EE, base + (size_t)1536*EE, EE, EE);
            // W1 [512,100] -> W1Tp [128,512];  W2 [100,512] -> W2Tp [512,128]
            pad_transpose_kernel<<<dim3(HIDP/32, EE/32), tb>>>(
                W1 + (size_t)l*EE*HIDN, gW1Tp + (size_t)l*HIDP*EE, EE, HIDN, EE, HIDP);
            pad_transpose_kernel<<<dim3(EE/32, HIDP/32), tb>>>(
                W2 + (size_t)l*HIDN*EE, gW2Tp + (size_t)l*EE*HIDP, HIDN, EE, HIDP, EE);
        }
        pad_b1_kernel<<<LL, HIDP>>>(b1, gb1p);
        transpose_kernel<<<dim3(VV/32, EE/32), tb>>>(Wlm, gWlmT, EE, VV);
    }

    embed_kernel<<<BT, 128>>>(idx, tok_emb, pos_emb, gx);

    for (int l = 0; l < LL; l++) {
        float* base = gWT + (size_t)l * 4 * EE * EE;
        const float* qkvT = base;
        const float* woT  = base + (size_t)1536*EE;
        float* attn_l = attn + (size_t)l * ATT_PER_L;

        ln_kernel<<<BT, 128>>>(gx, gh, ln1_g + l*EE, ln1_b + l*EE);

        // fused QKV: [4096,1536] = h @ [512,1536]
        mma_gemm<false,false,false,false><<<dim3(QKVS/128, BT/128), 256, GEMM_SMEM>>>(
            gh, qkvT, nullptr, nullptr, gqkv, BT, QKVS, EE);

        qk_mma<<<dim3(8, 8, BB*HH), 256, GEMM_SMEM>>>(gqkv, gS);
        softmax_kernel<<<BHT, 256>>>(gS, attn_l);
        vtrans_kernel<<<dim3(TT/32, EE/32, BB), dim3(32, 8)>>>(gqkv, gvT);
        av_mma<<<dim3(8, 1, BB*HH), 256, AV_SMEM>>>(attn_l, gvT, gy);

        // x = x + y @ Wo + bo
        mma_gemm<true,true,false,false><<<dim3(EE/128, BT/128), 256, GEMM_SMEM>>>(
            gy, woT, bo + l*EE, gx, gx, BT, EE, EE);

        ln_kernel<<<BT, 128>>>(gx, gh, ln2_g + l*EE, ln2_b + l*EE);

        // u = relu(h @ W1 + b1)   padded N=128
        mma_gemm<true,false,true,false><<<dim3(HIDP/128, BT/128), 256, GEMM_SMEM>>>(
            gh, gW1Tp + (size_t)l*HIDP*EE, gb1p + l*HIDP, nullptr, gu, BT, HIDP, EE);
        // x = x + u @ W2 + b2     padded K=128
        mma_gemm<true,true,false,false><<<dim3(EE/128, BT/128), 256, GEMM_SMEM>>>(
            gu, gW2Tp + (size_t)l*EE*HIDP, b2 + l*EE, gx, gx, BT, EE, HIDP);
    }

    ln_kernel<<<BT, 128>>>(gx, gh, lnf_g, lnf_b);
    // logits: 3-term bf16 + M-fastest grid for L2-friendly weight streaming
    mma_gemm<false,false,false,true><<<dim3(BT/128, VV/128), 256, GEMM_SMEM>>>(
        gh, gWlmT, nullptr, nullptr, logits, BT, VV, EE);
}

// round 9
// speedup vs baseline: 3.2314x; 1.0949x over previous
#include <cuda_runtime.h>
#include <cuda_bf16.h>
#include <cstdint>
#include <cstddef>

// Problem dims
#define BB 4
#define TT 1024
#define EE 512
#define HH 8
#define LL 4
#define VV 32000
#define HIDN 100
#define HIDP 128
#define HD 64
#define BT (BB*TT)          // 4096
#define BHT (BB*HH*TT)      // 32768
#define QKVS 1536           // packed qkv row stride
#define ATT_PER_L ((size_t)BB*HH*TT*TT)   // 33,554,432
#define LOGITS_N ((size_t)BT*VV)          // 131,072,000

// ---------------- scratch (device globals; no allocations allowed) ----------
// Packed format: uint32 = bf16_hi(f) | bf16_lo(f - hi) << 16
__device__ float    d_x[BT*EE];                   // residual stream (fp32)
__device__ uint32_t d_h[BT*EE];                   // packed LN output
__device__ uint32_t d_qkv[(size_t)BT*QKVS];       // packed q,k,v
__device__ uint32_t d_y[BT*EE];                   // packed attn output
__device__ uint32_t d_u[BT*HIDP];                 // packed ffn hidden
__device__ float    d_S[(size_t)BB*HH*TT*TT];     // raw scores fp32, 128 MB
__device__ uint32_t d_vT[(size_t)BB*EE*TT];       // packed V^T [b][e][s]
__device__ uint32_t d_WlmT[(size_t)VV*EE];        // packed Wlm^T [V,E]
__device__ uint32_t d_WT[(size_t)LL*4*EE*EE];     // packed per-layer qkvT+woT
__device__ uint32_t d_W1Tp[(size_t)LL*HIDP*EE];   // packed padded W1^T
__device__ uint32_t d_W2Tp[(size_t)LL*EE*HIDP];   // packed padded W2^T
__device__ float    d_b1p[LL*HIDP];

// ======================= helpers =============================================
#define TILE_F (128*36)           // elems per smem tile (padded rows)
#define GEMM_SMEM (4*TILE_F*4)
#define AV_SMEM  (2*(128*36 + 64*36)*4)

__device__ __forceinline__ uint32_t smem_u32(const void* p) {
    uint32_t a;
    asm("{ .reg .u64 t; cvta.to.shared.u64 t, %1; cvt.u32.u64 %0, t; }"
        : "=r"(a) : "l"(p));
    return a;
}
__device__ __forceinline__ void cp16(uint32_t saddr, const void* g) {
    asm volatile("cp.async.cg.shared.global [%0], [%1], 16;" :: "r"(saddr), "l"(g));
}
__device__ __forceinline__ uint32_t pack2_hi(float f0, float f1) {
    uint32_t r;
    asm("cvt.rn.bf16x2.f32 %0, %1, %2;" : "=r"(r) : "f"(f1), "f"(f0));
    return r;
}
__device__ __forceinline__ uint32_t pack2_lo(float f0, float f1, uint32_t hi) {
    float h0 = __uint_as_float(hi << 16);
    float h1 = __uint_as_float(hi & 0xffff0000u);
    uint32_t r;
    asm("cvt.rn.bf16x2.f32 %0, %1, %2;" : "=r"(r) : "f"(f1 - h1), "f"(f0 - h0));
    return r;
}
// pack one fp32 into hi|lo<<16
__device__ __forceinline__ uint32_t packelem(float f) {
    uint32_t H = pack2_hi(f, 0.0f);
    float hf = __uint_as_float(H << 16);
    uint32_t L = pack2_hi(f - hf, 0.0f);
    return (H & 0xffffu) | (L << 16);
}
// pack a consecutive pair (n, n+1) -> two packed words
__device__ __forceinline__ uint2 packpair(float f0, float f1) {
    uint32_t H = pack2_hi(f0, f1);
    uint32_t L = pack2_lo(f0, f1, H);
    return make_uint2(__byte_perm(H, L, 0x5410), __byte_perm(H, L, 0x7632));
}
// unpack two packed words (adjacent k) into bf16x2 hi and lo fragments
__device__ __forceinline__ void unpk(uint2 w, uint32_t& hi, uint32_t& lo) {
    hi = __byte_perm(w.x, w.y, 0x5410);
    lo = __byte_perm(w.x, w.y, 0x7632);
}
__device__ __forceinline__ void mma_bf16(float c[4], const uint32_t a[4], const uint32_t b[2]) {
    asm volatile(
        "mma.sync.aligned.m16n8k16.row.col.f32.bf16.bf16.f32 "
        "{%0,%1,%2,%3}, {%4,%5,%6,%7}, {%8,%9}, {%0,%1,%2,%3};"
        : "+f"(c[0]), "+f"(c[1]), "+f"(c[2]), "+f"(c[3])
        : "r"(a[0]), "r"(a[1]), "r"(a[2]), "r"(a[3]), "r"(b[0]), "r"(b[1]));
}

// ======================= packed bf16 mma GEMM (3-term) =======================
// C[M,N] = A[M,K] @ W[K,N]; A and BT_ are PACKED uint32, BT_ is [N,K].
template <bool BIAS, bool RES, bool RELU, bool SWAPG, bool PACKOUT>
__global__ void __launch_bounds__(256, 2)
mma_gemm(const uint32_t* __restrict__ A, const uint32_t* __restrict__ BT_,
         const float* __restrict__ bias, const float* __restrict__ res,
         float* __restrict__ C, int M, int N, int K) {
    extern __shared__ float smem_f[];
    uint32_t* As = (uint32_t*)smem_f;
    uint32_t* Bs = (uint32_t*)smem_f + 2*TILE_F;

    const int tid = threadIdx.x;
    const int wid = tid >> 5;
    const int lane = tid & 31;
    const int g = lane >> 2, q = lane & 3;
    const int wm = wid & 1, wn = wid >> 1;

    const int row0 = (SWAPG ? blockIdx.x : blockIdx.y) * 128;
    const int col0 = (SWAPG ? blockIdx.y : blockIdx.x) * 128;
    const uint32_t* Ap = A + (size_t)row0 * K;
    const uint32_t* Bp = BT_ + (size_t)col0 * K;

    const uint32_t sA0 = smem_u32(As);
    const uint32_t sB0 = smem_u32(Bs);

    const int NK = K >> 5;

    int lrow[4], lc4[4];
    #pragma unroll
    for (int j = 0; j < 4; j++) {
        int i = tid + j * 256;
        lrow[j] = i >> 3;
        lc4[j] = i & 7;
    }

    auto load_stage = [&](int buf, int kt) {
        const int k0 = kt << 5;
        const uint32_t offA = sA0 + buf * TILE_F * 4;
        const uint32_t offB = sB0 + buf * TILE_F * 4;
        #pragma unroll
        for (int j = 0; j < 4; j++) {
            uint32_t so = (uint32_t)(lrow[j] * 36 + lc4[j] * 4) * 4;
            cp16(offA + so, Ap + (size_t)lrow[j] * K + k0 + lc4[j] * 4);
            cp16(offB + so, Bp + (size_t)lrow[j] * K + k0 + lc4[j] * 4);
        }
        asm volatile("cp.async.commit_group;");
    };

    float acc[4][4][4];
    #pragma unroll
    for (int i = 0; i < 4; i++)
        #pragma unroll
        for (int j = 0; j < 4; j++)
            #pragma unroll
            for (int t = 0; t < 4; t++) acc[i][j][t] = 0.0f;

    load_stage(0, 0);

    int buf = 0;
    for (int kt = 0; kt < NK; kt++) {
        if (kt + 1 < NK) {
            load_stage(buf ^ 1, kt + 1);
            asm volatile("cp.async.wait_group 1;");
        } else {
            asm volatile("cp.async.wait_group 0;");
        }
        __syncthreads();

        const uint32_t* as = As + buf * TILE_F + (wm * 64 + g) * 36 + 2 * q;
        const uint32_t* bs = Bs + buf * TILE_F + (wn * 32 + g) * 36 + 2 * q;
        #pragma unroll
        for (int s = 0; s < 2; s++) {
            const int k0 = s * 16;
            uint32_t ah[4][4], al[4][4], bh[4][2], bl[4][2];
            #pragma unroll
            for (int i = 0; i < 4; i++) {
                const uint32_t* p = as + i * 16 * 36 + k0;
                unpk(*(const uint2*)(p),              ah[i][0], al[i][0]);
                unpk(*(const uint2*)(p + 8 * 36),     ah[i][1], al[i][1]);
                unpk(*(const uint2*)(p + 8),          ah[i][2], al[i][2]);
                unpk(*(const uint2*)(p + 8 * 36 + 8), ah[i][3], al[i][3]);
            }
            #pragma unroll
            for (int j = 0; j < 4; j++) {
                const uint32_t* p = bs + j * 8 * 36 + k0;
                unpk(*(const uint2*)(p),     bh[j][0], bl[j][0]);
                unpk(*(const uint2*)(p + 8), bh[j][1], bl[j][1]);
            }
            #pragma unroll
            for (int i = 0; i < 4; i++)
                #pragma unroll
                for (int j = 0; j < 4; j++) {
                    mma_bf16(acc[i][j], ah[i], bl[j]);
                    mma_bf16(acc[i][j], al[i], bh[j]);
                    mma_bf16(acc[i][j], ah[i], bh[j]);
                }
        }
        __syncthreads();
        buf ^= 1;
    }

    const int m0 = row0 + wm * 64 + g;
    const int n0 = col0 + wn * 32 + 2 * q;
    #pragma unroll
    for (int i = 0; i < 4; i++) {
        #pragma unroll
        for (int j = 0; j < 4; j++) {
            int c = n0 + j * 8;
            float b0 = 0.f, b1 = 0.f;
            if (BIAS) { b0 = bias[c]; b1 = bias[c + 1]; }
            #pragma unroll
            for (int hh = 0; hh < 2; hh++) {
                int r = m0 + i * 16 + hh * 8;
                float v0 = acc[i][j][hh * 2 + 0] + b0;
                float v1 = acc[i][j][hh * 2 + 1] + b1;
                if (RES) {
                    const float* rp = res + (size_t)r * N + c;
                    v0 += rp[0]; v1 += rp[1];
                }
                if (RELU) { v0 = fmaxf(v0, 0.f); v1 = fmaxf(v1, 0.f); }
                if (PACKOUT) {
                    uint2* cp = (uint2*)((uint32_t*)C + (size_t)r * N + c);
                    *cp = packpair(v0, v1);
                } else {
                    float2* cp = (float2*)(C + (size_t)r * N + c);
                    *cp = make_float2(v0, v1);
                }
            }
        }
    }
}

// ======================= QK^T via packed bf16 mma ============================
__global__ void __launch_bounds__(256, 2)
qk_mma(const uint32_t* __restrict__ qkv, float* __restrict__ S) {
    if (blockIdx.x > blockIdx.y) return;
    extern __shared__ float smem_f[];
    uint32_t* As = (uint32_t*)smem_f;
    uint32_t* Bs = (uint32_t*)smem_f + 2*TILE_F;

    const int tid = threadIdx.x;
    const int wid = tid >> 5;
    const int lane = tid & 31;
    const int g = lane >> 2, q = lane & 3;
    const int wm = wid & 1, wn = wid >> 1;

    const int row0 = blockIdx.y * 128;
    const int col0 = blockIdx.x * 128;
    const int b = blockIdx.z >> 3, h = blockIdx.z & 7;
    const uint32_t* Ap = qkv + ((size_t)b*TT + row0) * QKVS + h*HD;
    const uint32_t* Bp = qkv + 512 + ((size_t)b*TT + col0) * QKVS + h*HD;

    const uint32_t sA0 = smem_u32(As);
    const uint32_t sB0 = smem_u32(Bs);

    int lrow[4], lc4[4];
    #pragma unroll
    for (int j = 0; j < 4; j++) {
        int i = tid + j * 256;
        lrow[j] = i >> 3;
        lc4[j] = i & 7;
    }

    auto load_stage = [&](int buf, int kt) {
        const int k0 = kt << 5;
        const uint32_t offA = sA0 + buf * TILE_F * 4;
        const uint32_t offB = sB0 + buf * TILE_F * 4;
        #pragma unroll
        for (int j = 0; j < 4; j++) {
            uint32_t so = (uint32_t)(lrow[j] * 36 + lc4[j] * 4) * 4;
            cp16(offA + so, Ap + (size_t)lrow[j] * QKVS + k0 + lc4[j] * 4);
            cp16(offB + so, Bp + (size_t)lrow[j] * QKVS + k0 + lc4[j] * 4);
        }
        asm volatile("cp.async.commit_group;");
    };

    float acc[4][4][4];
    #pragma unroll
    for (int i = 0; i < 4; i++)
        #pragma unroll
        for (int j = 0; j < 4; j++)
            #pragma unroll
            for (int t = 0; t < 4; t++) acc[i][j][t] = 0.0f;

    load_stage(0, 0);

    int buf = 0;
    for (int kt = 0; kt < 2; kt++) {
        if (kt == 0) {
            load_stage(1, 1);
            asm volatile("cp.async.wait_group 1;");
        } else {
            asm volatile("cp.async.wait_group 0;");
        }
        __syncthreads();

        const uint32_t* as = As + buf * TILE_F + (wm * 64 + g) * 36 + 2 * q;
        const uint32_t* bs = Bs + buf * TILE_F + (wn * 32 + g) * 36 + 2 * q;
        #pragma unroll
        for (int s = 0; s < 2; s++) {
            const int k0 = s * 16;
            uint32_t ah[4][4], al[4][4], bh[4][2], bl[4][2];
            #pragma unroll
            for (int i = 0; i < 4; i++) {
                const uint32_t* p = as + i * 16 * 36 + k0;
                unpk(*(const uint2*)(p),              ah[i][0], al[i][0]);
                unpk(*(const uint2*)(p + 8 * 36),     ah[i][1], al[i][1]);
                unpk(*(const uint2*)(p + 8),          ah[i][2], al[i][2]);
                unpk(*(const uint2*)(p + 8 * 36 + 8), ah[i][3], al[i][3]);
            }
            #pragma unroll
            for (int j = 0; j < 4; j++) {
                const uint32_t* p = bs + j * 8 * 36 + k0;
                unpk(*(const uint2*)(p),     bh[j][0], bl[j][0]);
                unpk(*(const uint2*)(p + 8), bh[j][1], bl[j][1]);
            }
            #pragma unroll
            for (int i = 0; i < 4; i++)
                #pragma unroll
                for (int j = 0; j < 4; j++) {
                    mma_bf16(acc[i][j], ah[i], bl[j]);
                    mma_bf16(acc[i][j], al[i], bh[j]);
                    mma_bf16(acc[i][j], ah[i], bh[j]);
                }
        }
        __syncthreads();
        buf ^= 1;
    }

    float* Sp = S + (size_t)blockIdx.z * TT * TT;
    const int m0 = row0 + wm * 64 + g;
    const int n0 = col0 + wn * 32 + 2 * q;
    #pragma unroll
    for (int i = 0; i < 4; i++)
        #pragma unroll
        for (int j = 0; j < 4; j++) {
            int c = n0 + j * 8;
            #pragma unroll
            for (int hh = 0; hh < 2; hh++) {
                int r = m0 + i * 16 + hh * 8;
                float2* cp = (float2*)(Sp + (size_t)r * TT + c);
                *cp = make_float2(acc[i][j][hh*2+0] * 0.125f, acc[i][j][hh*2+1] * 0.125f);
            }
        }
}

// ======================= P @ V via bf16 mma ==================================
// A = P fp32 (split in-kernel), B = vT packed.
#define AV_AF (128*36)
#define AV_BF (64*36)
__global__ void __launch_bounds__(256, 2)
av_mma(const float* __restrict__ P, const uint32_t* __restrict__ vT,
       uint32_t* __restrict__ y) {
    extern __shared__ float smem_f[];
    float* As = smem_f;                              // fp32 P tile
    uint32_t* Bs = (uint32_t*)smem_f + 2*AV_AF;      // packed vT tile

    const int tid = threadIdx.x;
    const int wid = tid >> 5;
    const int lane = tid & 31;
    const int g = lane >> 2, q = lane & 3;
    const int wm = wid & 3, wn = wid >> 2;

    const int row0 = blockIdx.x * 128;
    const int b = blockIdx.z >> 3, h = blockIdx.z & 7;
    const float* Ap = P + (size_t)blockIdx.z * TT * TT + (size_t)row0 * TT;
    const uint32_t* Bp = vT + ((size_t)b*EE + h*HD) * TT;

    const uint32_t sA0 = smem_u32(As);
    const uint32_t sB0 = smem_u32(Bs);

    const int NK = (row0 >> 5) + 4;

    int arow[4], ac4[4], brow[2], bc4[2];
    #pragma unroll
    for (int j = 0; j < 4; j++) {
        int i = tid + j * 256;
        arow[j] = i >> 3; ac4[j] = i & 7;
    }
    #pragma unroll
    for (int j = 0; j < 2; j++) {
        int i = tid + j * 256;
        brow[j] = i >> 3; bc4[j] = i & 7;
    }

    auto load_stage = [&](int buf, int kt) {
        const int k0 = kt << 5;
        const uint32_t offA = sA0 + buf * AV_AF * 4;
        const uint32_t offB = sB0 + buf * AV_BF * 4;
        #pragma unroll
        for (int j = 0; j < 4; j++) {
            uint32_t so = (uint32_t)(arow[j] * 36 + ac4[j] * 4) * 4;
            cp16(offA + so, Ap + (size_t)arow[j] * TT + k0 + ac4[j] * 4);
        }
        #pragma unroll
        for (int j = 0; j < 2; j++) {
            uint32_t so = (uint32_t)(brow[j] * 36 + bc4[j] * 4) * 4;
            cp16(offB + so, Bp + (size_t)brow[j] * TT + k0 + bc4[j] * 4);
        }
        asm volatile("cp.async.commit_group;");
    };

    float acc[2][4][4];
    #pragma unroll
    for (int i = 0; i < 2; i++)
        #pragma unroll
        for (int j = 0; j < 4; j++)
            #pragma unroll
            for (int t = 0; t < 4; t++) acc[i][j][t] = 0.0f;

    load_stage(0, 0);

    int buf = 0;
    for (int kt = 0; kt < NK; kt++) {
        if (kt + 1 < NK) {
            load_stage(buf ^ 1, kt + 1);
            asm volatile("cp.async.wait_group 1;");
        } else {
            asm volatile("cp.async.wait_group 0;");
        }
        __syncthreads();

        const float* as = As + buf * AV_AF + (wm * 32 + g) * 36 + 2 * q;
        const uint32_t* bs = Bs + buf * AV_BF + (wn * 32 + g) * 36 + 2 * q;
        #pragma unroll
        for (int s = 0; s < 2; s++) {
            const int k0 = s * 16;
            uint32_t ah[2][4], al[2][4], bh[4][2], bl[4][2];
            #pragma unroll
            for (int i = 0; i < 2; i++) {
                const float* p = as + i * 16 * 36 + k0;
                float2 x0 = *(const float2*)(p);
                float2 x1 = *(const float2*)(p + 8 * 36);
                float2 x2 = *(const float2*)(p + 8);
                float2 x3 = *(const float2*)(p + 8 * 36 + 8);
                ah[i][0] = pack2_hi(x0.x, x0.y); al[i][0] = pack2_lo(x0.x, x0.y, ah[i][0]);
                ah[i][1] = pack2_hi(x1.x, x1.y); al[i][1] = pack2_lo(x1.x, x1.y, ah[i][1]);
                ah[i][2] = pack2_hi(x2.x, x2.y); al[i][2] = pack2_lo(x2.x, x2.y, ah[i][2]);
                ah[i][3] = pack2_hi(x3.x, x3.y); al[i][3] = pack2_lo(x3.x, x3.y, ah[i][3]);
            }
            #pragma unroll
            for (int j = 0; j < 4; j++) {
                const uint32_t* p = bs + j * 8 * 36 + k0;
                unpk(*(const uint2*)(p),     bh[j][0], bl[j][0]);
                unpk(*(const uint2*)(p + 8), bh[j][1], bl[j][1]);
            }
            #pragma unroll
            for (int i = 0; i < 2; i++)
                #pragma unroll
                for (int j = 0; j < 4; j++) {
                    mma_bf16(acc[i][j], ah[i], bl[j]);
                    mma_bf16(acc[i][j], al[i], bh[j]);
                    mma_bf16(acc[i][j], ah[i], bh[j]);
                }
        }
        __syncthreads();
        buf ^= 1;
    }

    const int m0 = row0 + wm * 32 + g;
    const int n0 = wn * 32 + 2 * q;
    #pragma unroll
    for (int i = 0; i < 2; i++)
        #pragma unroll
        for (int j = 0; j < 4; j++) {
            int c = n0 + j * 8;
            #pragma unroll
            for (int hh = 0; hh < 2; hh++) {
                int r = m0 + i * 16 + hh * 8;
                uint2* cp = (uint2*)(y + ((size_t)b*TT + r) * EE + h*HD + c);
                *cp = packpair(acc[i][j][hh*2+0], acc[i][j][hh*2+1]);
            }
        }
}

// ---------------- transpose + pack: W[K,N] -> WT_packed[N,K] -----------------
__global__ void transpose_pack_kernel(const float* __restrict__ W, uint32_t* __restrict__ WT,
                                      int K, int N) {
    __shared__ float t[32][33];
    int n0 = blockIdx.x * 32, k0 = blockIdx.y * 32;
    int x = threadIdx.x, y = threadIdx.y;
    #pragma unroll
    for (int j = 0; j < 32; j += 8)
        t[y + j][x] = W[(size_t)(k0 + y + j) * N + n0 + x];
    __syncthreads();
    #pragma unroll
    for (int j = 0; j < 32; j += 8)
        WT[(size_t)(n0 + y + j) * K + k0 + x] = packelem(t[x][y + j]);
}

// padded transpose + pack (zero fill)
__global__ void pad_transpose_pack_kernel(const float* __restrict__ W, uint32_t* __restrict__ WT,
                                          int K, int N, int Kp, int Np) {
    __shared__ float t[32][33];
    int n0 = blockIdx.x * 32, k0 = blockIdx.y * 32;
    int x = threadIdx.x, y = threadIdx.y;
    #pragma unroll
    for (int j = 0; j < 32; j += 8) {
        int kk = k0 + y + j, nn = n0 + x;
        t[y + j][x] = (kk < K && nn < N) ? W[(size_t)kk * N + nn] : 0.0f;
    }
    __syncthreads();
    #pragma unroll
    for (int j = 0; j < 32; j += 8)
        WT[(size_t)(n0 + y + j) * Kp + k0 + x] = packelem(t[x][y + j]);
}

__global__ void pad_b1_kernel(const float* __restrict__ b1, float* __restrict__ b1p) {
    int l = blockIdx.x, tid = threadIdx.x;
    b1p[l * HIDP + tid] = (tid < HIDN) ? b1[l * HIDN + tid] : 0.0f;
}

// transpose packed V -> vT[b][e][s]
__global__ void vtrans_kernel(const uint32_t* __restrict__ qkv, uint32_t* __restrict__ vT) {
    __shared__ uint32_t t[32][33];
    int s0 = blockIdx.x * 32, e0 = blockIdx.y * 32, b = blockIdx.z;
    int x = threadIdx.x, y = threadIdx.y;
    #pragma unroll
    for (int j = 0; j < 32; j += 8)
        t[y + j][x] = qkv[((size_t)b*TT + s0 + y + j) * QKVS + 1024 + e0 + x];
    __syncthreads();
    #pragma unroll
    for (int j = 0; j < 32; j += 8)
        vT[((size_t)b*EE + e0 + y + j) * TT + s0 + x] = t[x][y + j];
}

// ---------------- embed ------------------------------------------------------
__global__ void embed_kernel(const int* __restrict__ idx,
                             const float* __restrict__ tok,
                             const float* __restrict__ pos,
                             float* __restrict__ x) {
    int row = blockIdx.x;
    int t = row & (TT - 1);
    int token = idx[row];
    const float4* tp = (const float4*)(tok + (size_t)token * EE);
    const float4* pp = (const float4*)(pos + (size_t)t * EE);
    float4* xp = (float4*)(x + (size_t)row * EE);
    int c = threadIdx.x;
    float4 a = tp[c], b = pp[c];
    xp[c] = make_float4(a.x + b.x, a.y + b.y, a.z + b.z, a.w + b.w);
}

// ---------------- layernorm -> PACKED output --------------------------------
__global__ void ln_kernel(const float* __restrict__ x, uint32_t* __restrict__ out,
                          const float* __restrict__ g, const float* __restrict__ b) {
    int row = blockIdx.x;
    int tid = threadIdx.x;
    const float4* xp = (const float4*)(x + (size_t)row * EE);
    float4 v = xp[tid];
    float s = v.x + v.y + v.z + v.w;
    __shared__ float red[4];
    for (int o = 16; o; o >>= 1) s += __shfl_xor_sync(~0u, s, o);
    if ((tid & 31) == 0) red[tid >> 5] = s;
    __syncthreads();
    float mean = (red[0] + red[1] + red[2] + red[3]) / (float)EE;
    float dx = v.x - mean, dy = v.y - mean, dz = v.z - mean, dw = v.w - mean;
    float ss = dx*dx + dy*dy + dz*dz + dw*dw;
    __syncthreads();
    for (int o = 16; o; o >>= 1) ss += __shfl_xor_sync(~0u, ss, o);
    if ((tid & 31) == 0) red[tid >> 5] = ss;
    __syncthreads();
    float var = (red[0] + red[1] + red[2] + red[3]) / (float)EE;
    float inv = 1.0f / sqrtf(var + 1e-5f);
    const float4* gp = (const float4*)g;
    const float4* bp = (const float4*)b;
    float4 gg = gp[tid], bb = bp[tid];
    float o0 = dx*inv*gg.x + bb.x, o1 = dy*inv*gg.y + bb.y;
    float o2 = dz*inv*gg.z + bb.z, o3 = dw*inv*gg.w + bb.w;
    uint2 p01 = packpair(o0, o1);
    uint2 p23 = packpair(o2, o3);
    uint4* op = (uint4*)(out + (size_t)row * EE);
    op[tid] = make_uint4(p01.x, p01.y, p23.x, p23.y);
}

// ---------------- causal softmax row -> writes attn map into d_out ----------
__global__ void softmax_kernel(const float* __restrict__ S, float* __restrict__ out) {
    int row = blockIdx.x;
    int t = row & (TT - 1);
    const float* sp = S + (size_t)row * TT;
    float* op = out + (size_t)row * TT;
    int tid = threadIdx.x;
    float vals[4];
    float m = -1e30f;
    #pragma unroll
    for (int i = 0; i < 4; i++) {
        int s = tid + i * 256;
        vals[i] = (s <= t) ? sp[s] : -1e30f;
        m = fmaxf(m, vals[i]);
    }
    __shared__ float red[8];
    for (int o = 16; o; o >>= 1) m = fmaxf(m, __shfl_xor_sync(~0u, m, o));
    if ((tid & 31) == 0) red[tid >> 5] = m;
    __syncthreads();
    m = red[0];
    #pragma unroll
    for (int i = 1; i < 8; i++) m = fmaxf(m, red[i]);
    float e[4];
    float ssum = 0.0f;
    #pragma unroll
    for (int i = 0; i < 4; i++) {
        int s = tid + i * 256;
        e[i] = (s <= t) ? expf(vals[i] - m) : 0.0f;
        ssum += e[i];
    }
    __syncthreads();
    for (int o = 16; o; o >>= 1) ssum += __shfl_xor_sync(~0u, ssum, o);
    if ((tid & 31) == 0) red[tid >> 5] = ssum;
    __syncthreads();
    float tot = 0.0f;
    #pragma unroll
    for (int i = 0; i < 8; i++) tot += red[i];
    float inv = 1.0f / tot;
    #pragma unroll
    for (int i = 0; i < 4; i++) {
        int s = tid + i * 256;
        op[s] = e[i] * inv;
    }
}

// ---------------- host orchestration ----------------------------------------
extern "C" void kernel_launch(void* const* d_in, const int* in_sizes, int n_in,
                              void* d_out, int out_size) {
    (void)in_sizes; (void)n_in; (void)out_size;
    const int*   idx     = (const int*)  d_in[0];
    const float* tok_emb = (const float*)d_in[1];
    const float* pos_emb = (const float*)d_in[2];
    const float* ln1_g   = (const float*)d_in[3];
    const float* ln1_b   = (const float*)d_in[4];
    const float* Wq      = (const float*)d_in[5];
    const float* Wk      = (const float*)d_in[6];
    const float* Wv      = (const float*)d_in[7];
    const float* Wo      = (const float*)d_in[8];
    const float* bo      = (const float*)d_in[9];
    const float* ln2_g   = (const float*)d_in[10];
    const float* ln2_b   = (const float*)d_in[11];
    const float* W1      = (const float*)d_in[12];
    const float* b1      = (const float*)d_in[13];
    const float* W2      = (const float*)d_in[14];
    const float* b2      = (const float*)d_in[15];
    const float* lnf_g   = (const float*)d_in[16];
    const float* lnf_b   = (const float*)d_in[17];
    const float* Wlm     = (const float*)d_in[18];

    float* out    = (float*)d_out;
    float* logits = out;
    float* attn   = out + LOGITS_N;

    float *gx, *gS, *gb1p;
    uint32_t *gh, *gqkv, *gy, *gu, *gvT, *gWlmT, *gWT, *gW1Tp, *gW2Tp;
    cudaGetSymbolAddress((void**)&gx, d_x);
    cudaGetSymbolAddress((void**)&gh, d_h);
    cudaGetSymbolAddress((void**)&gqkv, d_qkv);
    cudaGetSymbolAddress((void**)&gy, d_y);
    cudaGetSymbolAddress((void**)&gu, d_u);
    cudaGetSymbolAddress((void**)&gS, d_S);
    cudaGetSymbolAddress((void**)&gvT, d_vT);
    cudaGetSymbolAddress((void**)&gWlmT, d_WlmT);
    cudaGetSymbolAddress((void**)&gWT, d_WT);
    cudaGetSymbolAddress((void**)&gW1Tp, d_W1Tp);
    cudaGetSymbolAddress((void**)&gW2Tp, d_W2Tp);
    cudaGetSymbolAddress((void**)&gb1p, d_b1p);

    cudaFuncSetAttribute(mma_gemm<false,false,false,false,true>,
                         cudaFuncAttributeMaxDynamicSharedMemorySize, GEMM_SMEM);
    cudaFuncSetAttribute(mma_gemm<true,true,false,false,false>,
                         cudaFuncAttributeMaxDynamicSharedMemorySize, GEMM_SMEM);
    cudaFuncSetAttribute(mma_gemm<true,false,true,false,true>,
                         cudaFuncAttributeMaxDynamicSharedMemorySize, GEMM_SMEM);
    cudaFuncSetAttribute(mma_gemm<false,false,false,true,false>,
                         cudaFuncAttributeMaxDynamicSharedMemorySize, GEMM_SMEM);
    cudaFuncSetAttribute(qk_mma, cudaFuncAttributeMaxDynamicSharedMemorySize, GEMM_SMEM);
    cudaFuncSetAttribute(av_mma, cudaFuncAttributeMaxDynamicSharedMemorySize, AV_SMEM);

    // Weight prep: transpose + pack
    {
        dim3 tb(32, 8);
        for (int l = 0; l < LL; l++) {
            uint32_t* base = gWT + (size_t)l * 4 * EE * EE;
            transpose_pack_kernel<<<dim3(EE/32, EE/32), tb>>>(Wq + (size_t)l*EE*EE, base,                 EE, EE);
            transpose_pack_kernel<<<dim3(EE/32, EE/32), tb>>>(Wk + (size_t)l*EE*EE, base + (size_t)512*EE, EE, EE);
            transpose_pack_kernel<<<dim3(EE/32, EE/32), tb>>>(Wv + (size_t)l*EE*EE, base + (size_t)1024*EE, EE, EE);
            transpose_pack_kernel<<<dim3(EE/32, EE/32), tb>>>(Wo + (size_t)l*EE*EE, base + (size_t)1536*EE, EE, EE);
            pad_transpose_pack_kernel<<<dim3(HIDP/32, EE/32), tb>>>(
                W1 + (size_t)l*EE*HIDN, gW1Tp + (size_t)l*HIDP*EE, EE, HIDN, EE, HIDP);
            pad_transpose_pack_kernel<<<dim3(EE/32, HIDP/32), tb>>>(
                W2 + (size_t)l*HIDN*EE, gW2Tp + (size_t)l*EE*HIDP, HIDN, EE, HIDP, EE);
        }
        pad_b1_kernel<<<LL, HIDP>>>(b1, gb1p);
        transpose_pack_kernel<<<dim3(VV/32, EE/32), tb>>>(Wlm, gWlmT, EE, VV);
    }

    embed_kernel<<<BT, 128>>>(idx, tok_emb, pos_emb, gx);

    for (int l = 0; l < LL; l++) {
        uint32_t* base = gWT + (size_t)l * 4 * EE * EE;
        const uint32_t* qkvT = base;
        const uint32_t* woT  = base + (size_t)1536*EE;
        float* attn_l = attn + (size_t)l * ATT_PER_L;

        ln_kernel<<<BT, 128>>>(gx, gh, ln1_g + l*EE, ln1_b + l*EE);

        // fused QKV (packed in, packed out)
        mma_gemm<false,false,false,false,true><<<dim3(QKVS/128, BT/128), 256, GEMM_SMEM>>>(
            gh, qkvT, nullptr, nullptr, (float*)gqkv, BT, QKVS, EE);

        qk_mma<<<dim3(8, 8, BB*HH), 256, GEMM_SMEM>>>(gqkv, gS);
        softmax_kernel<<<BHT, 256>>>(gS, attn_l);
        vtrans_kernel<<<dim3(TT/32, EE/32, BB), dim3(32, 8)>>>(gqkv, gvT);
        av_mma<<<dim3(8, 1, BB*HH), 256, AV_SMEM>>>(attn_l, gvT, gy);

        // x = x + y @ Wo + bo  (packed A, fp32 out + residual)
        mma_gemm<true,true,false,false,false><<<dim3(EE/128, BT/128), 256, GEMM_SMEM>>>(
            gy, woT, bo + l*EE, gx, gx, BT, EE, EE);

        ln_kernel<<<BT, 128>>>(gx, gh, ln2_g + l*EE, ln2_b + l*EE);

        // u = relu(h @ W1 + b1)  packed out
        mma_gemm<true,false,true,false,true><<<dim3(HIDP/128, BT/128), 256, GEMM_SMEM>>>(
            gh, gW1Tp + (size_t)l*HIDP*EE, gb1p + l*HIDP, nullptr, (float*)gu, BT, HIDP, EE);
        // x = x + u @ W2 + b2
        mma_gemm<true,true,false,false,false><<<dim3(EE/128, BT/128), 256, GEMM_SMEM>>>(
            gu, gW2Tp + (size_t)l*EE*HIDP, b2 + l*EE, gx, gx, BT, EE, HIDP);
    }

    ln_kernel<<<BT, 128>>>(gx, gh, lnf_g, lnf_b);
    // logits: packed A/B, fp32 out, M-fastest grid
    mma_gemm<false,false,false,true,false><<<dim3(BT/128, VV/128), 256, GEMM_SMEM>>>(
        gh, gWlmT, nullptr, nullptr, logits, BT, VV, EE);
}